// round 1
// baseline (speedup 1.0000x reference)
#include <cuda_runtime.h>

#define B_  4
#define S_  1024
#define D_  1024
#define H_  16
#define DK_ 64

// Scratch for projected Q,K,V in [B,H,S,DK] layout (16 MB each, device globals
// per allocation rules).
__device__ float g_Q[B_ * H_ * S_ * DK_];
__device__ float g_K[B_ * H_ * S_ * DK_];
__device__ float g_V[B_ * H_ * S_ * DK_];

// ---------------------------------------------------------------------------
// Projection GEMM: out[b,h,s,d] = sum_k X[(b,s)][k] * W[n][k] + bias[n]
// (C = X · Wᵀ, both operands K-contiguous). BM=BN=128, BK=8, 256 threads,
// 8x8 register microtiles. Writes directly into head-split [B,H,S,DK] layout.
// ---------------------------------------------------------------------------
__global__ __launch_bounds__(256, 2)
void proj_kernel(const float* __restrict__ X, const float* __restrict__ W,
                 const float* __restrict__ bias, int sel) {
    __shared__ float As[8][132];   // pitch 132 floats: 16B-aligned rows, no write conflicts
    __shared__ float Bs[8][132];

    float* out = (sel == 0) ? g_Q : ((sel == 1) ? g_K : g_V);

    const int K = D_;
    const int m0 = blockIdx.y * 128;
    const int n0 = blockIdx.x * 128;
    const int tid = threadIdx.x;
    const int tx = tid & 15;       // 16 col-groups of 8
    const int ty = tid >> 4;       // 16 row-groups of 8

    const int lm = tid >> 1;       // 0..127: tile row loaded by this thread
    const int lk = (tid & 1) << 2; // 0 or 4: k offset (float4)

    const float* Xp = X + (size_t)(m0 + lm) * K + lk;
    const float* Wp = W + (size_t)(n0 + lm) * K + lk;

    float acc[8][8];
#pragma unroll
    for (int i = 0; i < 8; i++)
#pragma unroll
        for (int j = 0; j < 8; j++) acc[i][j] = 0.f;

    for (int k0 = 0; k0 < K; k0 += 8) {
        float4 a = *(const float4*)(Xp + k0);
        float4 b = *(const float4*)(Wp + k0);
        As[lk + 0][lm] = a.x; As[lk + 1][lm] = a.y;
        As[lk + 2][lm] = a.z; As[lk + 3][lm] = a.w;
        Bs[lk + 0][lm] = b.x; Bs[lk + 1][lm] = b.y;
        Bs[lk + 2][lm] = b.z; Bs[lk + 3][lm] = b.w;
        __syncthreads();

#pragma unroll
        for (int kk = 0; kk < 8; kk++) {
            float ar[8], br[8];
            *(float4*)&ar[0] = *(const float4*)&As[kk][ty * 8];
            *(float4*)&ar[4] = *(const float4*)&As[kk][ty * 8 + 4];
            *(float4*)&br[0] = *(const float4*)&Bs[kk][tx * 8];
            *(float4*)&br[4] = *(const float4*)&Bs[kk][tx * 8 + 4];
#pragma unroll
            for (int i = 0; i < 8; i++)
#pragma unroll
                for (int j = 0; j < 8; j++)
                    acc[i][j] += ar[i] * br[j];
        }
        __syncthreads();
    }

    // Epilogue: bias + scatter into [B,H,S,DK]
#pragma unroll
    for (int i = 0; i < 8; i++) {
        const int m = m0 + ty * 8 + i;
        const int b = m >> 10;
        const int s = m & 1023;
#pragma unroll
        for (int j = 0; j < 8; j++) {
            const int n = n0 + tx * 8 + j;
            const int h = n >> 6;
            const int d = n & 63;
            out[(((size_t)(b * H_ + h) * S_ + s) << 6) + d] = acc[i][j] + bias[n];
        }
    }
}

// ---------------------------------------------------------------------------
// Flash attention, causal + key-padding mask, fp32, online softmax.
// One block = one (b, h, 64-row q tile). 64 threads, each owns an 8x8 microtile.
// Smem: Qs[64][65], KPs[64][65] (K tile, reused as P tile), Vs[64][64], mask[64].
// ---------------------------------------------------------------------------
#define ATT_SMEM_BYTES ((2 * 64 * 65 + 64 * 64) * 4 + 64 * 4)

__global__ __launch_bounds__(64)
void attn_kernel(const int* __restrict__ amask, float* __restrict__ out) {
    extern __shared__ float sm[];
    float* Qs  = sm;                 // [64][65]
    float* KPs = sm + 64 * 65;       // [64][65]  (K tile, then P tile)
    float* Vs  = sm + 2 * 64 * 65;   // [64][64]
    int*   msk = (int*)(sm + 2 * 64 * 65 + 64 * 64);  // [64]

    const int bh = blockIdx.y;       // b*H + h
    const int b  = bh >> 4;
    const int h  = bh & 15;
    const int q0 = blockIdx.x * 64;
    const int tid = threadIdx.x;
    const int tx = tid & 7;          // 8 col-groups of 8
    const int ty = tid >> 3;         // 8 row-groups of 8

    const float* Qg = g_Q + (size_t)bh * S_ * DK_;
    const float* Kg = g_K + (size_t)bh * S_ * DK_;
    const float* Vg = g_V + (size_t)bh * S_ * DK_;

    // Load Q tile (coalesced global reads; conflict-free smem writes, pitch 65)
    for (int i = tid; i < 64 * 64; i += 64) {
        const int r = i >> 6, c = i & 63;
        Qs[r * 65 + c] = Qg[(size_t)(q0 + r) * 64 + c];
    }

    float acc[8][8];
    float m_i[8], l_i[8];
#pragma unroll
    for (int i = 0; i < 8; i++) {
        m_i[i] = -1e30f;
        l_i[i] = 0.f;
#pragma unroll
        for (int j = 0; j < 8; j++) acc[i][j] = 0.f;
    }

    const int kend = q0 + 64;  // causal: only k-tiles with kt < q0+64
    for (int kt = 0; kt < kend; kt += 64) {
        // Load K and V tiles + mask
        for (int i = tid; i < 64 * 64; i += 64) {
            const int r = i >> 6, c = i & 63;
            KPs[r * 65 + c] = Kg[(size_t)(kt + r) * 64 + c];
            Vs[r * 64 + c]  = Vg[(size_t)(kt + r) * 64 + c];
        }
        msk[tid] = amask[b * S_ + kt + tid];
        __syncthreads();

        // S = Q Kᵀ (8x8 per thread)
        float s[8][8];
#pragma unroll
        for (int i = 0; i < 8; i++)
#pragma unroll
            for (int j = 0; j < 8; j++) s[i][j] = 0.f;

#pragma unroll 8
        for (int kk = 0; kk < 64; kk++) {
            float qr[8], kr[8];
#pragma unroll
            for (int i = 0; i < 8; i++) qr[i] = Qs[(ty * 8 + i) * 65 + kk];
#pragma unroll
            for (int j = 0; j < 8; j++) kr[j] = KPs[(tx * 8 + j) * 65 + kk];
#pragma unroll
            for (int i = 0; i < 8; i++)
#pragma unroll
                for (int j = 0; j < 8; j++)
                    s[i][j] += qr[i] * kr[j];
        }

        // Scale + causal + padding mask
#pragma unroll
        for (int j = 0; j < 8; j++) {
            const int kg = kt + tx * 8 + j;
            const bool dead = (msk[tx * 8 + j] == 0);
#pragma unroll
            for (int i = 0; i < 8; i++) {
                const int qg = q0 + ty * 8 + i;
                const float v = s[i][j] * 0.125f;
                s[i][j] = (dead || kg > qg) ? -1e30f : v;
            }
        }

        __syncthreads();  // all threads done reading KPs as K

        // Online softmax (row reductions across the 8 tx lanes) + write P
#pragma unroll
        for (int i = 0; i < 8; i++) {
            float rm = s[i][0];
#pragma unroll
            for (int j = 1; j < 8; j++) rm = fmaxf(rm, s[i][j]);
            rm = fmaxf(rm, __shfl_xor_sync(0xffffffffu, rm, 1));
            rm = fmaxf(rm, __shfl_xor_sync(0xffffffffu, rm, 2));
            rm = fmaxf(rm, __shfl_xor_sync(0xffffffffu, rm, 4));

            const float mnew = fmaxf(m_i[i], rm);
            const float corr = __expf(m_i[i] - mnew);  // underflows to 0 on first tile

            float rs = 0.f;
#pragma unroll
            for (int j = 0; j < 8; j++) {
                const float p = __expf(s[i][j] - mnew);
                s[i][j] = p;
                rs += p;
            }
            rs += __shfl_xor_sync(0xffffffffu, rs, 1);
            rs += __shfl_xor_sync(0xffffffffu, rs, 2);
            rs += __shfl_xor_sync(0xffffffffu, rs, 4);

            l_i[i] = l_i[i] * corr + rs;
            m_i[i] = mnew;
#pragma unroll
            for (int j = 0; j < 8; j++) acc[i][j] *= corr;
            // P into the K buffer (safe after barrier)
#pragma unroll
            for (int j = 0; j < 8; j++)
                KPs[(ty * 8 + i) * 65 + tx * 8 + j] = s[i][j];
        }
        __syncthreads();

        // O += P · V
#pragma unroll 8
        for (int k = 0; k < 64; k++) {
            float pk[8];
#pragma unroll
            for (int i = 0; i < 8; i++) pk[i] = KPs[(ty * 8 + i) * 65 + k];
            float vr[8];
            *(float4*)&vr[0] = *(const float4*)&Vs[k * 64 + tx * 8];
            *(float4*)&vr[4] = *(const float4*)&Vs[k * 64 + tx * 8 + 4];
#pragma unroll
            for (int i = 0; i < 8; i++)
#pragma unroll
                for (int j = 0; j < 8; j++)
                    acc[i][j] += pk[i] * vr[j];
        }
        __syncthreads();
    }

    // Epilogue: O / l, write to [B, S, H*DK]
#pragma unroll
    for (int i = 0; i < 8; i++) {
        const float inv = 1.f / l_i[i];
        const int qg = q0 + ty * 8 + i;
        float* op = out + ((size_t)b * S_ + qg) * D_ + h * DK_ + tx * 8;
#pragma unroll
        for (int j = 0; j < 8; j++) op[j] = acc[i][j] * inv;
    }
}

// ---------------------------------------------------------------------------
// Launch
// ---------------------------------------------------------------------------
extern "C" void kernel_launch(void* const* d_in, const int* in_sizes, int n_in,
                              void* d_out, int out_size) {
    const float* query = (const float*)d_in[0];
    const float* key   = (const float*)d_in[1];
    const float* value = (const float*)d_in[2];
    const int*   amask = (const int*)d_in[3];
    const float* Wq    = (const float*)d_in[4];
    const float* bq    = (const float*)d_in[5];
    const float* Wk    = (const float*)d_in[6];
    const float* bk    = (const float*)d_in[7];
    const float* Wv    = (const float*)d_in[8];
    const float* bv    = (const float*)d_in[9];
    float* out = (float*)d_out;

    const dim3 pg(D_ / 128, (B_ * S_) / 128);  // (8, 32)
    proj_kernel<<<pg, 256>>>(query, Wq, bq, 0);
    proj_kernel<<<pg, 256>>>(key,   Wk, bk, 1);
    proj_kernel<<<pg, 256>>>(value, Wv, bv, 2);

    cudaFuncSetAttribute(attn_kernel,
                         cudaFuncAttributeMaxDynamicSharedMemorySize,
                         ATT_SMEM_BYTES);
    attn_kernel<<<dim3(S_ / 64, B_ * H_), 64, ATT_SMEM_BYTES>>>(amask, out);
}

// round 6
// speedup vs baseline: 1.9293x; 1.9293x over previous
#include <cuda_runtime.h>
#include <cstdint>

#define B_  4
#define S_  1024
#define D_  1024
#define H_  16
#define DK_ 64

// Scratch: projected Q,K,V in [B,H,S,DK]; tf32-rounded copies of X and W.
__device__ float g_Q[B_ * H_ * S_ * DK_];
__device__ float g_K[B_ * H_ * S_ * DK_];
__device__ float g_V[B_ * H_ * S_ * DK_];
__device__ float g_Xr[3ull * (B_ * S_) * D_];   // rounded query/key/value
__device__ float g_Wr[3ull * D_ * D_];          // rounded Wq/Wk/Wv

// ---------------------------------------------------------------------------
// Helpers (sm_80-era PTX only: cp.async, ldmatrix, mma.sync tf32)
// ---------------------------------------------------------------------------
__device__ __forceinline__ uint32_t smem_to_u32(const void* p) {
    uint32_t a;
    asm("{ .reg .u64 t; cvta.to.shared.u64 t, %1; cvt.u32.u64 %0, t; }"
        : "=r"(a) : "l"(p));
    return a;
}

#define CP_ASYNC16(dst, src) \
    asm volatile("cp.async.cg.shared.global [%0], [%1], 16;" \
                 :: "r"((uint32_t)(dst)), "l"(src) : "memory")
#define CP_COMMIT() asm volatile("cp.async.commit_group;" ::: "memory")
#define CP_WAIT1()  asm volatile("cp.async.wait_group 1;" ::: "memory")
#define CP_WAIT0()  asm volatile("cp.async.wait_group 0;" ::: "memory")

__device__ __forceinline__ void ldsm4(uint32_t* r, uint32_t addr) {
    asm volatile("ldmatrix.sync.aligned.m8n8.x4.shared.b16 {%0,%1,%2,%3}, [%4];"
                 : "=r"(r[0]), "=r"(r[1]), "=r"(r[2]), "=r"(r[3]) : "r"(addr));
}

__device__ __forceinline__ void mma_tf32(float* c, const uint32_t* a,
                                         uint32_t b0, uint32_t b1) {
    asm volatile(
        "mma.sync.aligned.m16n8k8.row.col.f32.tf32.tf32.f32 "
        "{%0,%1,%2,%3}, {%4,%5,%6,%7}, {%8,%9}, {%0,%1,%2,%3};"
        : "+f"(c[0]), "+f"(c[1]), "+f"(c[2]), "+f"(c[3])
        : "r"(a[0]), "r"(a[1]), "r"(a[2]), "r"(a[3]), "r"(b0), "r"(b1));
}

// cvt to tf32 produces a .b32 destination.
__device__ __forceinline__ float rtf32(float x) {
    uint32_t r;
    asm("cvt.rna.tf32.f32 %0, %1;" : "=r"(r) : "f"(x));
    return __uint_as_float(r);
}

// ---------------------------------------------------------------------------
// Pre-pass: round fp32 -> tf32 (RNA) so mma.sync sees unbiased operands.
// ---------------------------------------------------------------------------
__global__ void tf32_round_kernel(const float4* __restrict__ s,
                                  float4* __restrict__ d, int n4) {
    for (int i = blockIdx.x * blockDim.x + threadIdx.x; i < n4;
         i += gridDim.x * blockDim.x) {
        float4 v = s[i];
        v.x = rtf32(v.x); v.y = rtf32(v.y);
        v.z = rtf32(v.z); v.w = rtf32(v.w);
        d[i] = v;
    }
}

// ---------------------------------------------------------------------------
// tf32 mma.sync projection GEMM: out = X (4096x1024) · Wᵀ (1024x1024) + bias
// BM=BN=128, BK=32 (128B rows, 16B-chunk XOR swizzle), double-buffered
// cp.async, 8 warps of 64x32 microtiles (m16n8k8). Scatter to [B,H,S,DK].
// ---------------------------------------------------------------------------
#define PROJ_SMEM (2 * 32768 + 512)   // 2 stages (A16K+B16K) + bias

__device__ __forceinline__ void load_chunk(uint32_t stA, uint32_t stB,
                                           const float* __restrict__ X,
                                           const float* __restrict__ W,
                                           int m0, int n0, int k0, int tid) {
#pragma unroll
    for (int i = 0; i < 4; i++) {
        const int q   = tid + i * 256;       // 0..1023
        const int row = q >> 3;              // 0..127
        const int c   = q & 7;               // 16B chunk in 128B row
        const uint32_t off = (uint32_t)(row * 128) + ((c ^ (row & 7)) << 4);
        CP_ASYNC16(stA + off, X + (size_t)(m0 + row) * D_ + k0 + c * 4);
        CP_ASYNC16(stB + off, W + (size_t)(n0 + row) * D_ + k0 + c * 4);
    }
}

__global__ __launch_bounds__(256, 2)
void proj_mma(const float* __restrict__ bq, const float* __restrict__ bk,
              const float* __restrict__ bv) {
    extern __shared__ char smem[];
    const uint32_t sb = smem_to_u32(smem);

    const int z = blockIdx.z;
    const float* X    = g_Xr + (size_t)z * (B_ * S_) * D_;
    const float* W    = g_Wr + (size_t)z * D_ * D_;
    const float* bias = (z == 0) ? bq : ((z == 1) ? bk : bv);
    float*       out  = (z == 0) ? g_Q : ((z == 1) ? g_K : g_V);

    const int m0 = blockIdx.y * 128;
    const int n0 = blockIdx.x * 128;
    const int tid = threadIdx.x;
    const int wid = tid >> 5;
    const int lid = tid & 31;
    const int wm = wid >> 2;          // 0..1  (64-row band)
    const int wn = wid & 3;           // 0..3  (32-col band)

    float* sbias = (float*)(smem + 65536);
    if (tid < 128) sbias[tid] = bias[n0 + tid];

    // ldmatrix lane constants (matrix id = lid>>3, row-in-matrix = lid&7)
    const int mrow = lid & 7;
    const int msel = lid >> 3;
    const int aRowHalf   = (msel & 1) * 8;   // A: matrices 0/1 = rows, 2/3 = +k
    const int aChunkHalf = msel >> 1;
    const int bRowHalf   = (msel >> 1) * 8;  // B: matrices 0/1 = k halves
    const int bChunkHalf = msel & 1;

    float acc[4][4][4];
#pragma unroll
    for (int i = 0; i < 4; i++)
#pragma unroll
        for (int j = 0; j < 4; j++)
#pragma unroll
            for (int r = 0; r < 4; r++) acc[i][j][r] = 0.f;

    load_chunk(sb, sb + 16384, X, W, m0, n0, 0, tid);
    CP_COMMIT();

    for (int c = 0; c < 32; c++) {
        const int cur = c & 1;
        const uint32_t stA = sb + cur * 32768;
        const uint32_t stB = stA + 16384;
        if (c + 1 < 32) {
            const uint32_t nx = sb + (cur ^ 1) * 32768;
            load_chunk(nx, nx + 16384, X, W, m0, n0, (c + 1) * 32, tid);
            CP_COMMIT();
            CP_WAIT1();
        } else {
            CP_WAIT0();
        }
        __syncthreads();

#pragma unroll
        for (int ks = 0; ks < 4; ks++) {
            uint32_t a[4][4];
#pragma unroll
            for (int mf = 0; mf < 4; mf++) {
                const int row = wm * 64 + mf * 16 + aRowHalf + mrow;
                ldsm4(a[mf], stA + row * 128 +
                              (((2 * ks + aChunkHalf) ^ mrow) << 4));
            }
            uint32_t bb[2][4];
#pragma unroll
            for (int nf2 = 0; nf2 < 2; nf2++) {
                const int row = wn * 32 + nf2 * 16 + bRowHalf + mrow;
                ldsm4(bb[nf2], stB + row * 128 +
                               (((2 * ks + bChunkHalf) ^ mrow) << 4));
            }
#pragma unroll
            for (int mf = 0; mf < 4; mf++)
#pragma unroll
                for (int nf = 0; nf < 4; nf++)
                    mma_tf32(acc[mf][nf], a[mf],
                             bb[nf >> 1][(nf & 1) * 2],
                             bb[nf >> 1][(nf & 1) * 2 + 1]);
        }
        __syncthreads();
    }

    // Epilogue: bias + scatter (float2 stores, [B,H,S,DK])
    const int g = lid >> 2, t = lid & 3;
#pragma unroll
    for (int mf = 0; mf < 4; mf++) {
        const int m = m0 + wm * 64 + mf * 16 + g;
        const int b = m >> 10;
        const int s = m & 1023;
#pragma unroll
        for (int nf = 0; nf < 4; nf++) {
            const int nl = wn * 32 + nf * 8 + 2 * t;
            const int n = n0 + nl;
            const int h = n >> 6;
            const int d = n & 63;
            const float b0v = sbias[nl], b1v = sbias[nl + 1];
            const size_t base = (((size_t)(b * H_ + h) * S_) + s) * 64 + d;
            float2 v0 = {acc[mf][nf][0] + b0v, acc[mf][nf][1] + b1v};
            float2 v1 = {acc[mf][nf][2] + b0v, acc[mf][nf][3] + b1v};
            *(float2*)(out + base) = v0;
            *(float2*)(out + base + 8 * 64) = v1;   // row m+8 (same b,h)
        }
    }
}

// ---------------------------------------------------------------------------
// Flash attention, causal + key-padding mask, fp32, online softmax.
// (unchanged from R1 — converts to mma.sync next round)
// ---------------------------------------------------------------------------
#define ATT_SMEM_BYTES ((2 * 64 * 65 + 64 * 64) * 4 + 64 * 4)

__global__ __launch_bounds__(64)
void attn_kernel(const int* __restrict__ amask, float* __restrict__ out) {
    extern __shared__ float sm[];
    float* Qs  = sm;
    float* KPs = sm + 64 * 65;
    float* Vs  = sm + 2 * 64 * 65;
    int*   msk = (int*)(sm + 2 * 64 * 65 + 64 * 64);

    const int bh = blockIdx.y;
    const int b  = bh >> 4;
    const int h  = bh & 15;
    const int q0 = blockIdx.x * 64;
    const int tid = threadIdx.x;
    const int tx = tid & 7;
    const int ty = tid >> 3;

    const float* Qg = g_Q + (size_t)bh * S_ * DK_;
    const float* Kg = g_K + (size_t)bh * S_ * DK_;
    const float* Vg = g_V + (size_t)bh * S_ * DK_;

    for (int i = tid; i < 64 * 64; i += 64) {
        const int r = i >> 6, c = i & 63;
        Qs[r * 65 + c] = Qg[(size_t)(q0 + r) * 64 + c];
    }

    float acc[8][8];
    float m_i[8], l_i[8];
#pragma unroll
    for (int i = 0; i < 8; i++) {
        m_i[i] = -1e30f;
        l_i[i] = 0.f;
#pragma unroll
        for (int j = 0; j < 8; j++) acc[i][j] = 0.f;
    }

    const int kend = q0 + 64;
    for (int kt = 0; kt < kend; kt += 64) {
        for (int i = tid; i < 64 * 64; i += 64) {
            const int r = i >> 6, c = i & 63;
            KPs[r * 65 + c] = Kg[(size_t)(kt + r) * 64 + c];
            Vs[r * 64 + c]  = Vg[(size_t)(kt + r) * 64 + c];
        }
        msk[tid] = amask[b * S_ + kt + tid];
        __syncthreads();

        float s[8][8];
#pragma unroll
        for (int i = 0; i < 8; i++)
#pragma unroll
            for (int j = 0; j < 8; j++) s[i][j] = 0.f;

#pragma unroll 8
        for (int kk = 0; kk < 64; kk++) {
            float qr[8], kr[8];
#pragma unroll
            for (int i = 0; i < 8; i++) qr[i] = Qs[(ty * 8 + i) * 65 + kk];
#pragma unroll
            for (int j = 0; j < 8; j++) kr[j] = KPs[(tx * 8 + j) * 65 + kk];
#pragma unroll
            for (int i = 0; i < 8; i++)
#pragma unroll
                for (int j = 0; j < 8; j++)
                    s[i][j] += qr[i] * kr[j];
        }

#pragma unroll
        for (int j = 0; j < 8; j++) {
            const int kg = kt + tx * 8 + j;
            const bool dead = (msk[tx * 8 + j] == 0);
#pragma unroll
            for (int i = 0; i < 8; i++) {
                const int qg = q0 + ty * 8 + i;
                const float v = s[i][j] * 0.125f;
                s[i][j] = (dead || kg > qg) ? -1e30f : v;
            }
        }

        __syncthreads();

#pragma unroll
        for (int i = 0; i < 8; i++) {
            float rm = s[i][0];
#pragma unroll
            for (int j = 1; j < 8; j++) rm = fmaxf(rm, s[i][j]);
            rm = fmaxf(rm, __shfl_xor_sync(0xffffffffu, rm, 1));
            rm = fmaxf(rm, __shfl_xor_sync(0xffffffffu, rm, 2));
            rm = fmaxf(rm, __shfl_xor_sync(0xffffffffu, rm, 4));

            const float mnew = fmaxf(m_i[i], rm);
            const float corr = __expf(m_i[i] - mnew);

            float rs = 0.f;
#pragma unroll
            for (int j = 0; j < 8; j++) {
                const float p = __expf(s[i][j] - mnew);
                s[i][j] = p;
                rs += p;
            }
            rs += __shfl_xor_sync(0xffffffffu, rs, 1);
            rs += __shfl_xor_sync(0xffffffffu, rs, 2);
            rs += __shfl_xor_sync(0xffffffffu, rs, 4);

            l_i[i] = l_i[i] * corr + rs;
            m_i[i] = mnew;
#pragma unroll
            for (int j = 0; j < 8; j++) acc[i][j] *= corr;
#pragma unroll
            for (int j = 0; j < 8; j++)
                KPs[(ty * 8 + i) * 65 + tx * 8 + j] = s[i][j];
        }
        __syncthreads();

#pragma unroll 8
        for (int k = 0; k < 64; k++) {
            float pk[8];
#pragma unroll
            for (int i = 0; i < 8; i++) pk[i] = KPs[(ty * 8 + i) * 65 + k];
            float vr[8];
            *(float4*)&vr[0] = *(const float4*)&Vs[k * 64 + tx * 8];
            *(float4*)&vr[4] = *(const float4*)&Vs[k * 64 + tx * 8 + 4];
#pragma unroll
            for (int i = 0; i < 8; i++)
#pragma unroll
                for (int j = 0; j < 8; j++)
                    acc[i][j] += pk[i] * vr[j];
        }
        __syncthreads();
    }

#pragma unroll
    for (int i = 0; i < 8; i++) {
        const float inv = 1.f / l_i[i];
        const int qg = q0 + ty * 8 + i;
        float* op = out + ((size_t)b * S_ + qg) * D_ + h * DK_ + tx * 8;
#pragma unroll
        for (int j = 0; j < 8; j++) op[j] = acc[i][j] * inv;
    }
}

// ---------------------------------------------------------------------------
// Launch
// ---------------------------------------------------------------------------
extern "C" void kernel_launch(void* const* d_in, const int* in_sizes, int n_in,
                              void* d_out, int out_size) {
    const float* query = (const float*)d_in[0];
    const float* key   = (const float*)d_in[1];
    const float* value = (const float*)d_in[2];
    const int*   amask = (const int*)d_in[3];
    const float* Wq    = (const float*)d_in[4];
    const float* bq    = (const float*)d_in[5];
    const float* Wk    = (const float*)d_in[6];
    const float* bk    = (const float*)d_in[7];
    const float* Wv    = (const float*)d_in[8];
    const float* bv    = (const float*)d_in[9];
    float* out = (float*)d_out;

    float* xr;  cudaGetSymbolAddress((void**)&xr, g_Xr);
    float* wr;  cudaGetSymbolAddress((void**)&wr, g_Wr);

    const int nx4 = (B_ * S_ * D_) / 4;     // 1,048,576 float4
    const int nw4 = (D_ * D_) / 4;          // 262,144 float4
    tf32_round_kernel<<<1024, 256>>>((const float4*)query, (float4*)(xr + 0ull * B_ * S_ * D_), nx4);
    tf32_round_kernel<<<1024, 256>>>((const float4*)key,   (float4*)(xr + 1ull * B_ * S_ * D_), nx4);
    tf32_round_kernel<<<1024, 256>>>((const float4*)value, (float4*)(xr + 2ull * B_ * S_ * D_), nx4);
    tf32_round_kernel<<<512, 256>>>((const float4*)Wq, (float4*)(wr + 0ull * D_ * D_), nw4);
    tf32_round_kernel<<<512, 256>>>((const float4*)Wk, (float4*)(wr + 1ull * D_ * D_), nw4);
    tf32_round_kernel<<<512, 256>>>((const float4*)Wv, (float4*)(wr + 2ull * D_ * D_), nw4);

    cudaFuncSetAttribute(proj_mma, cudaFuncAttributeMaxDynamicSharedMemorySize,
                         PROJ_SMEM);
    proj_mma<<<dim3(8, 32, 3), 256, PROJ_SMEM>>>(bq, bk, bv);

    cudaFuncSetAttribute(attn_kernel,
                         cudaFuncAttributeMaxDynamicSharedMemorySize,
                         ATT_SMEM_BYTES);
    attn_kernel<<<dim3(S_ / 64, B_ * H_), 64, ATT_SMEM_BYTES>>>(amask, out);
}

// round 8
// speedup vs baseline: 2.8790x; 1.4923x over previous
#include <cuda_runtime.h>
#include <cstdint>

#define B_  4
#define S_  1024
#define D_  1024
#define H_  16
#define DK_ 64

// Scratch: projected Q,K in [B,H,S,DK]; V transposed [B,H,DK,S];
// tf32-rounded copies of X and W.
__device__ float g_Q[B_ * H_ * S_ * DK_];
__device__ float g_K[B_ * H_ * S_ * DK_];
__device__ float g_Vt[B_ * H_ * DK_ * S_];
__device__ float g_Xr[3ull * (B_ * S_) * D_];
__device__ float g_Wr[3ull * D_ * D_];

// ---------------------------------------------------------------------------
// Helpers (sm_80-era PTX only: cp.async, ldmatrix, mma.sync tf32)
// ---------------------------------------------------------------------------
__device__ __forceinline__ uint32_t smem_to_u32(const void* p) {
    uint32_t a;
    asm("{ .reg .u64 t; cvta.to.shared.u64 t, %1; cvt.u32.u64 %0, t; }"
        : "=r"(a) : "l"(p));
    return a;
}

#define CP_ASYNC16(dst, src) \
    asm volatile("cp.async.cg.shared.global [%0], [%1], 16;" \
                 :: "r"((uint32_t)(dst)), "l"(src) : "memory")
#define CP_COMMIT() asm volatile("cp.async.commit_group;" ::: "memory")
#define CP_WAIT1()  asm volatile("cp.async.wait_group 1;" ::: "memory")
#define CP_WAIT0()  asm volatile("cp.async.wait_group 0;" ::: "memory")

__device__ __forceinline__ void ldsm4(uint32_t* r, uint32_t addr) {
    asm volatile("ldmatrix.sync.aligned.m8n8.x4.shared.b16 {%0,%1,%2,%3}, [%4];"
                 : "=r"(r[0]), "=r"(r[1]), "=r"(r[2]), "=r"(r[3]) : "r"(addr));
}

__device__ __forceinline__ void mma_tf32(float* c, const uint32_t* a,
                                         uint32_t b0, uint32_t b1) {
    asm volatile(
        "mma.sync.aligned.m16n8k8.row.col.f32.tf32.tf32.f32 "
        "{%0,%1,%2,%3}, {%4,%5,%6,%7}, {%8,%9}, {%0,%1,%2,%3};"
        : "+f"(c[0]), "+f"(c[1]), "+f"(c[2]), "+f"(c[3])
        : "r"(a[0]), "r"(a[1]), "r"(a[2]), "r"(a[3]), "r"(b0), "r"(b1));
}

__device__ __forceinline__ float rtf32(float x) {
    uint32_t r;
    asm("cvt.rna.tf32.f32 %0, %1;" : "=r"(r) : "f"(x));
    return __uint_as_float(r);
}

// ---------------------------------------------------------------------------
// Pre-pass: round fp32 -> tf32 (RNA).
// ---------------------------------------------------------------------------
__global__ void tf32_round_kernel(const float4* __restrict__ s,
                                  float4* __restrict__ d, int n4) {
    for (int i = blockIdx.x * blockDim.x + threadIdx.x; i < n4;
         i += gridDim.x * blockDim.x) {
        float4 v = s[i];
        v.x = rtf32(v.x); v.y = rtf32(v.y);
        v.z = rtf32(v.z); v.w = rtf32(v.w);
        d[i] = v;
    }
}

// ---------------------------------------------------------------------------
// tf32 mma.sync projection GEMM (validated R6). V written transposed.
// ---------------------------------------------------------------------------
#define PROJ_SMEM (2 * 32768 + 512)

__device__ __forceinline__ void load_chunk(uint32_t stA, uint32_t stB,
                                           const float* __restrict__ X,
                                           const float* __restrict__ W,
                                           int m0, int n0, int k0, int tid) {
#pragma unroll
    for (int i = 0; i < 4; i++) {
        const int q   = tid + i * 256;
        const int row = q >> 3;
        const int c   = q & 7;
        const uint32_t off = (uint32_t)(row * 128) + ((c ^ (row & 7)) << 4);
        CP_ASYNC16(stA + off, X + (size_t)(m0 + row) * D_ + k0 + c * 4);
        CP_ASYNC16(stB + off, W + (size_t)(n0 + row) * D_ + k0 + c * 4);
    }
}

__global__ __launch_bounds__(256, 2)
void proj_mma(const float* __restrict__ bq, const float* __restrict__ bk,
              const float* __restrict__ bv) {
    extern __shared__ char smem[];
    const uint32_t sb = smem_to_u32(smem);

    const int z = blockIdx.z;
    const float* X    = g_Xr + (size_t)z * (B_ * S_) * D_;
    const float* W    = g_Wr + (size_t)z * D_ * D_;
    const float* bias = (z == 0) ? bq : ((z == 1) ? bk : bv);

    const int m0 = blockIdx.y * 128;
    const int n0 = blockIdx.x * 128;
    const int tid = threadIdx.x;
    const int wid = tid >> 5;
    const int lid = tid & 31;
    const int wm = wid >> 2;
    const int wn = wid & 3;

    float* sbias = (float*)(smem + 65536);
    if (tid < 128) sbias[tid] = bias[n0 + tid];

    const int mrow = lid & 7;
    const int msel = lid >> 3;
    const int aRowHalf   = (msel & 1) * 8;
    const int aChunkHalf = msel >> 1;
    const int bRowHalf   = (msel >> 1) * 8;
    const int bChunkHalf = msel & 1;

    float acc[4][4][4];
#pragma unroll
    for (int i = 0; i < 4; i++)
#pragma unroll
        for (int j = 0; j < 4; j++)
#pragma unroll
            for (int r = 0; r < 4; r++) acc[i][j][r] = 0.f;

    load_chunk(sb, sb + 16384, X, W, m0, n0, 0, tid);
    CP_COMMIT();

    for (int c = 0; c < 32; c++) {
        const int cur = c & 1;
        const uint32_t stA = sb + cur * 32768;
        const uint32_t stB = stA + 16384;
        if (c + 1 < 32) {
            const uint32_t nx = sb + (cur ^ 1) * 32768;
            load_chunk(nx, nx + 16384, X, W, m0, n0, (c + 1) * 32, tid);
            CP_COMMIT();
            CP_WAIT1();
        } else {
            CP_WAIT0();
        }
        __syncthreads();

#pragma unroll
        for (int ks = 0; ks < 4; ks++) {
            uint32_t a[4][4];
#pragma unroll
            for (int mf = 0; mf < 4; mf++) {
                const int row = wm * 64 + mf * 16 + aRowHalf + mrow;
                ldsm4(a[mf], stA + row * 128 +
                              (((2 * ks + aChunkHalf) ^ mrow) << 4));
            }
            uint32_t bb[2][4];
#pragma unroll
            for (int nf2 = 0; nf2 < 2; nf2++) {
                const int row = wn * 32 + nf2 * 16 + bRowHalf + mrow;
                ldsm4(bb[nf2], stB + row * 128 +
                               (((2 * ks + bChunkHalf) ^ mrow) << 4));
            }
#pragma unroll
            for (int mf = 0; mf < 4; mf++)
#pragma unroll
                for (int nf = 0; nf < 4; nf++)
                    mma_tf32(acc[mf][nf], a[mf],
                             bb[nf >> 1][(nf & 1) * 2],
                             bb[nf >> 1][(nf & 1) * 2 + 1]);
        }
        __syncthreads();
    }

    // Epilogue: bias + scatter. Q,K -> [B,H,S,DK]; V -> transposed [B,H,DK,S].
    const int g = lid >> 2, t = lid & 3;
#pragma unroll
    for (int mf = 0; mf < 4; mf++) {
        const int m = m0 + wm * 64 + mf * 16 + g;
        const int b = m >> 10;
        const int s = m & 1023;
#pragma unroll
        for (int nf = 0; nf < 4; nf++) {
            const int nl = wn * 32 + nf * 8 + 2 * t;
            const int n = n0 + nl;
            const int h = n >> 6;
            const int d = n & 63;
            const float b0v = sbias[nl], b1v = sbias[nl + 1];
            if (z == 2) {
                const size_t gb = ((size_t)(b * H_ + h) * DK_ + d) * S_;
                g_Vt[gb + s]            = acc[mf][nf][0] + b0v;
                g_Vt[gb + S_ + s]       = acc[mf][nf][1] + b1v;
                g_Vt[gb + s + 8]        = acc[mf][nf][2] + b0v;
                g_Vt[gb + S_ + s + 8]   = acc[mf][nf][3] + b1v;
            } else {
                float* out = (z == 0) ? g_Q : g_K;
                const size_t base = (((size_t)(b * H_ + h) * S_) + s) * 64 + d;
                float2 v0 = {acc[mf][nf][0] + b0v, acc[mf][nf][1] + b1v};
                float2 v1 = {acc[mf][nf][2] + b0v, acc[mf][nf][3] + b1v};
                *(float2*)(out + base) = v0;
                *(float2*)(out + base + 8 * 64) = v1;
            }
        }
    }
}

// ---------------------------------------------------------------------------
// Flash attention on mma.sync tf32 with 3xTF32 split (full fp32-like precision)
// CTA = 128 q-rows x one (b,h). 8 warps, each m=16 rows, full n=64, full DK.
// ---------------------------------------------------------------------------
// smem byte offsets
#define AS_KH 0          // K hi  [64 seq][64 dk]  16KB (2 swizzled 8KB blocks)
#define AS_KL 16384      // K lo
#define AS_VH 32768      // Vt hi [64 dk][64 seq]
#define AS_VL 49152      // Vt lo
#define AS_P  65536      // per warp 8KB: Ph @ wq*8192, Pl @ +4096
#define AS_MSK 131072
#define ATT_SMEM (131072 + 256)

// [64][64] fp32 tile, two swizzled 8KB blocks (block = col>>5)
__device__ __forceinline__ uint32_t tadr64(uint32_t base, int row, int col) {
    return base + ((col >> 5) << 13) + row * 128 +
           (((((col & 31) >> 2)) ^ (row & 7)) << 4) + ((col & 3) << 2);
}

__global__ __launch_bounds__(256, 1)
void attn_mma(const int* __restrict__ amask, float* __restrict__ out) {
    extern __shared__ char smem[];
    const uint32_t sb = smem_to_u32(smem);
    int* msk = (int*)(smem + AS_MSK);

    const int bh = blockIdx.y;
    const int b  = bh >> 4;
    const int h  = bh & 15;
    const int qb = (gridDim.x - 1) - blockIdx.x;   // heavy blocks first
    const int q0 = qb * 128;
    const int tid = threadIdx.x;
    const int wq  = tid >> 5;        // warp owns rows [q0+wq*16, +16)
    const int lid = tid & 31;
    const int g = lid >> 2, t = lid & 3;

    const int mrow = lid & 7;
    const int msel = lid >> 3;
    const int aRowHalf   = (msel & 1) * 8;
    const int aChunkHalf = msel >> 1;
    const int bRowHalf   = (msel >> 1) * 8;
    const int bChunkHalf = msel & 1;

    const float* Qg  = g_Q  + (size_t)bh * S_ * DK_;
    const float* Kg  = g_K  + (size_t)bh * S_ * DK_;
    const float* Vtg = g_Vt + (size_t)bh * DK_ * S_;

    // ---- Q A-fragments (hi/lo), loaded once straight into registers.
    // m16n8k8 A layout: a0=(g, c), a1=(g+8, c), a2=(g, c+4), a3=(g+8, c+4)
    uint32_t qh[8][4], ql[8][4];
    {
        const float* q0p = Qg + (size_t)(q0 + wq * 16 + g) * 64;
        const float* q8p = q0p + 8 * 64;
#pragma unroll
        for (int ks = 0; ks < 8; ks++) {
            float x0 = q0p[ks * 8 + t];
            float x1 = q8p[ks * 8 + t];
            float x2 = q0p[ks * 8 + t + 4];
            float x3 = q8p[ks * 8 + t + 4];
            float h0 = rtf32(x0), h1 = rtf32(x1), h2 = rtf32(x2), h3 = rtf32(x3);
            qh[ks][0] = __float_as_uint(h0); ql[ks][0] = __float_as_uint(x0 - h0);
            qh[ks][1] = __float_as_uint(h1); ql[ks][1] = __float_as_uint(x1 - h1);
            qh[ks][2] = __float_as_uint(h2); ql[ks][2] = __float_as_uint(x2 - h2);
            qh[ks][3] = __float_as_uint(h3); ql[ks][3] = __float_as_uint(x3 - h3);
        }
    }

    float o[8][4];
    float m0r = -1e30f, m1r = -1e30f, l0r = 0.f, l1r = 0.f;
#pragma unroll
    for (int nf = 0; nf < 8; nf++)
#pragma unroll
        for (int r = 0; r < 4; r++) o[nf][r] = 0.f;

    const int row0 = q0 + wq * 16 + g;
    const int row1 = row0 + 8;
    const int ntiles = (qb + 1) * 2;

    for (int it = 0; it < ntiles; it++) {
        const int kt = it * 64;
        __syncthreads();   // protect prior iteration's K/V readers

        // ---- load K and Vt tiles, split hi/lo into swizzled smem
#pragma unroll
        for (int i = 0; i < 4; i++) {
            const int e = tid + i * 256;        // 0..1023 float4 slots
            const int row = e >> 4;
            const int col = (e & 15) * 4;
            float4 kv = *(const float4*)(Kg + (size_t)(kt + row) * 64 + col);
            float4 kh, kl;
            kh.x = rtf32(kv.x); kl.x = kv.x - kh.x;
            kh.y = rtf32(kv.y); kl.y = kv.y - kh.y;
            kh.z = rtf32(kv.z); kl.z = kv.z - kh.z;
            kh.w = rtf32(kv.w); kl.w = kv.w - kh.w;
            *(float4*)(smem + (tadr64(AS_KH, row, col))) = kh;
            *(float4*)(smem + (tadr64(AS_KL, row, col))) = kl;
            float4 vv = *(const float4*)(Vtg + (size_t)row * S_ + kt + col);
            float4 vh, vl;
            vh.x = rtf32(vv.x); vl.x = vv.x - vh.x;
            vh.y = rtf32(vv.y); vl.y = vv.y - vh.y;
            vh.z = rtf32(vv.z); vl.z = vv.z - vh.z;
            vh.w = rtf32(vv.w); vl.w = vv.w - vh.w;
            *(float4*)(smem + (tadr64(AS_VH, row, col))) = vh;
            *(float4*)(smem + (tadr64(AS_VL, row, col))) = vl;
        }
        if (tid < 64) msk[tid] = amask[b * S_ + kt + tid];
        __syncthreads();

        // ---- S = Q K^T  (3xTF32)
        float s[8][4];
#pragma unroll
        for (int nf = 0; nf < 8; nf++)
#pragma unroll
            for (int r = 0; r < 4; r++) s[nf][r] = 0.f;

#pragma unroll
        for (int ks = 0; ks < 8; ks++) {
            const uint32_t coff = ((ks >> 2) << 13) +
                                  (((2 * (ks & 3) + bChunkHalf) ^ mrow) << 4);
#pragma unroll
            for (int nf2 = 0; nf2 < 4; nf2++) {
                const int row = nf2 * 16 + bRowHalf + mrow;
                uint32_t bhh[4], bll[4];
                ldsm4(bhh, sb + AS_KH + row * 128 + coff);
                ldsm4(bll, sb + AS_KL + row * 128 + coff);
#pragma unroll
                for (int half = 0; half < 2; half++) {
                    const int nf = nf2 * 2 + half;
                    mma_tf32(s[nf], qh[ks], bhh[half * 2], bhh[half * 2 + 1]);
                    mma_tf32(s[nf], qh[ks], bll[half * 2], bll[half * 2 + 1]);
                    mma_tf32(s[nf], ql[ks], bhh[half * 2], bhh[half * 2 + 1]);
                }
            }
        }

        // ---- mask + scale
#pragma unroll
        for (int nf = 0; nf < 8; nf++) {
            const int c0 = nf * 8 + 2 * t;
            const int kg0 = kt + c0, kg1 = kg0 + 1;
            const bool d0 = (msk[c0] == 0), d1 = (msk[c0 + 1] == 0);
            s[nf][0] = (d0 || kg0 > row0) ? -1e30f : s[nf][0] * 0.125f;
            s[nf][1] = (d1 || kg1 > row0) ? -1e30f : s[nf][1] * 0.125f;
            s[nf][2] = (d0 || kg0 > row1) ? -1e30f : s[nf][2] * 0.125f;
            s[nf][3] = (d1 || kg1 > row1) ? -1e30f : s[nf][3] * 0.125f;
        }

        // ---- online softmax (warp-local: reduce over 4 t-lanes)
        float rm0 = -1e30f, rm1 = -1e30f;
#pragma unroll
        for (int nf = 0; nf < 8; nf++) {
            rm0 = fmaxf(rm0, fmaxf(s[nf][0], s[nf][1]));
            rm1 = fmaxf(rm1, fmaxf(s[nf][2], s[nf][3]));
        }
        rm0 = fmaxf(rm0, __shfl_xor_sync(0xffffffffu, rm0, 1));
        rm0 = fmaxf(rm0, __shfl_xor_sync(0xffffffffu, rm0, 2));
        rm1 = fmaxf(rm1, __shfl_xor_sync(0xffffffffu, rm1, 1));
        rm1 = fmaxf(rm1, __shfl_xor_sync(0xffffffffu, rm1, 2));

        const float mn0 = fmaxf(m0r, rm0), mn1 = fmaxf(m1r, rm1);
        const float cr0 = __expf(m0r - mn0), cr1 = __expf(m1r - mn1);
        m0r = mn0; m1r = mn1;

        const uint32_t pH = sb + AS_P + wq * 8192;
        const uint32_t pL = pH + 4096;
        float rs0 = 0.f, rs1 = 0.f;
#pragma unroll
        for (int nf = 0; nf < 8; nf++) {
            const int col = nf * 8 + 2 * t;
            float p0 = __expf(s[nf][0] - mn0);
            float p1 = __expf(s[nf][1] - mn0);
            float p2 = __expf(s[nf][2] - mn1);
            float p3 = __expf(s[nf][3] - mn1);
            rs0 += p0 + p1;  rs1 += p2 + p3;
            float h0 = rtf32(p0), h1 = rtf32(p1), h2 = rtf32(p2), h3 = rtf32(p3);
            // P tile per warp: [16 rows][64 cols], 2KB blocks (block = col>>5)
            const uint32_t o0 = ((col >> 5) << 11) + g * 128 +
                                ((((col & 31) >> 2) ^ (g & 7)) << 4) + ((col & 3) << 2);
            const uint32_t o1 = ((col >> 5) << 11) + (g + 8) * 128 +
                                ((((col & 31) >> 2) ^ ((g + 8) & 7)) << 4) + ((col & 3) << 2);
            *(float2*)(smem + (pH - sb) + o0) = make_float2(h0, h1);
            *(float2*)(smem + (pL - sb) + o0) = make_float2(p0 - h0, p1 - h1);
            *(float2*)(smem + (pH - sb) + o1) = make_float2(h2, h3);
            *(float2*)(smem + (pL - sb) + o1) = make_float2(p2 - h2, p3 - h3);
        }
        rs0 += __shfl_xor_sync(0xffffffffu, rs0, 1);
        rs0 += __shfl_xor_sync(0xffffffffu, rs0, 2);
        rs1 += __shfl_xor_sync(0xffffffffu, rs1, 1);
        rs1 += __shfl_xor_sync(0xffffffffu, rs1, 2);
        l0r = l0r * cr0 + rs0;
        l1r = l1r * cr1 + rs1;

#pragma unroll
        for (int nf = 0; nf < 8; nf++) {
            o[nf][0] *= cr0; o[nf][1] *= cr0;
            o[nf][2] *= cr1; o[nf][3] *= cr1;
        }
        __syncwarp();   // P staging visible to this warp's ldsm

        // ---- O += P V  (3xTF32; A-frags from P staging, B-frags from Vt)
#pragma unroll
        for (int ks = 0; ks < 8; ks++) {
            uint32_t ah[4], al[4];
            const uint32_t ao = ((ks >> 2) << 11) + (aRowHalf + mrow) * 128 +
                                (((2 * (ks & 3) + aChunkHalf) ^ mrow) << 4);
            ldsm4(ah, pH + ao);
            ldsm4(al, pL + ao);
            const uint32_t coff = ((ks >> 2) << 13) +
                                  (((2 * (ks & 3) + bChunkHalf) ^ mrow) << 4);
#pragma unroll
            for (int nf2 = 0; nf2 < 4; nf2++) {
                const int row = nf2 * 16 + bRowHalf + mrow;
                uint32_t vhh[4], vll[4];
                ldsm4(vhh, sb + AS_VH + row * 128 + coff);
                ldsm4(vll, sb + AS_VL + row * 128 + coff);
#pragma unroll
                for (int half = 0; half < 2; half++) {
                    const int nf = nf2 * 2 + half;
                    mma_tf32(o[nf], ah, vhh[half * 2], vhh[half * 2 + 1]);
                    mma_tf32(o[nf], ah, vll[half * 2], vll[half * 2 + 1]);
                    mma_tf32(o[nf], al, vhh[half * 2], vhh[half * 2 + 1]);
                }
            }
        }
        __syncwarp();   // done with P staging before next overwrite
    }

    // ---- epilogue: O / l -> out [B, S, H*DK]
    const float i0 = 1.f / l0r, i1 = 1.f / l1r;
    float* o0p = out + ((size_t)b * S_ + row0) * D_ + h * DK_;
    float* o1p = out + ((size_t)b * S_ + row1) * D_ + h * DK_;
#pragma unroll
    for (int nf = 0; nf < 8; nf++) {
        const int d = nf * 8 + 2 * t;
        *(float2*)(o0p + d) = make_float2(o[nf][0] * i0, o[nf][1] * i0);
        *(float2*)(o1p + d) = make_float2(o[nf][2] * i1, o[nf][3] * i1);
    }
}

// ---------------------------------------------------------------------------
// Launch
// ---------------------------------------------------------------------------
extern "C" void kernel_launch(void* const* d_in, const int* in_sizes, int n_in,
                              void* d_out, int out_size) {
    const float* query = (const float*)d_in[0];
    const float* key   = (const float*)d_in[1];
    const float* value = (const float*)d_in[2];
    const int*   amask = (const int*)d_in[3];
    const float* Wq    = (const float*)d_in[4];
    const float* bq    = (const float*)d_in[5];
    const float* Wk    = (const float*)d_in[6];
    const float* bk    = (const float*)d_in[7];
    const float* Wv    = (const float*)d_in[8];
    const float* bv    = (const float*)d_in[9];
    float* out = (float*)d_out;

    float* xr;  cudaGetSymbolAddress((void**)&xr, g_Xr);
    float* wr;  cudaGetSymbolAddress((void**)&wr, g_Wr);

    const int nx4 = (B_ * S_ * D_) / 4;
    const int nw4 = (D_ * D_) / 4;
    tf32_round_kernel<<<1024, 256>>>((const float4*)query, (float4*)(xr + 0ull * B_ * S_ * D_), nx4);
    tf32_round_kernel<<<1024, 256>>>((const float4*)key,   (float4*)(xr + 1ull * B_ * S_ * D_), nx4);
    tf32_round_kernel<<<1024, 256>>>((const float4*)value, (float4*)(xr + 2ull * B_ * S_ * D_), nx4);
    tf32_round_kernel<<<512, 256>>>((const float4*)Wq, (float4*)(wr + 0ull * D_ * D_), nw4);
    tf32_round_kernel<<<512, 256>>>((const float4*)Wk, (float4*)(wr + 1ull * D_ * D_), nw4);
    tf32_round_kernel<<<512, 256>>>((const float4*)Wv, (float4*)(wr + 2ull * D_ * D_), nw4);

    cudaFuncSetAttribute(proj_mma, cudaFuncAttributeMaxDynamicSharedMemorySize,
                         PROJ_SMEM);
    proj_mma<<<dim3(8, 32, 3), 256, PROJ_SMEM>>>(bq, bk, bv);

    cudaFuncSetAttribute(attn_mma, cudaFuncAttributeMaxDynamicSharedMemorySize,
                         ATT_SMEM);
    attn_mma<<<dim3(S_ / 128, B_ * H_), 256, ATT_SMEM>>>(amask, out);
}

// round 9
// speedup vs baseline: 3.4862x; 1.2109x over previous
#include <cuda_runtime.h>
#include <cstdint>

#define B_  4
#define S_  1024
#define D_  1024
#define H_  16
#define DK_ 64
#define NX4 ((B_ * S_ * D_) / 4)
#define NW4 ((D_ * D_) / 4)

// Scratch: Q fp32, K pre-rounded tf32, V transposed + pre-split hi/lo,
// tf32-rounded copies of X and W.
__device__ float g_Q[B_ * H_ * S_ * DK_];
__device__ float g_K[B_ * H_ * S_ * DK_];
__device__ float g_Vth[B_ * H_ * DK_ * S_];
__device__ float g_Vtl[B_ * H_ * DK_ * S_];
__device__ float g_Xr[3ull * (B_ * S_) * D_];
__device__ float g_Wr[3ull * D_ * D_];

// ---------------------------------------------------------------------------
// Helpers (sm_80-era PTX only: cp.async, ldmatrix, mma.sync tf32)
// ---------------------------------------------------------------------------
__device__ __forceinline__ uint32_t smem_to_u32(const void* p) {
    uint32_t a;
    asm("{ .reg .u64 t; cvta.to.shared.u64 t, %1; cvt.u32.u64 %0, t; }"
        : "=r"(a) : "l"(p));
    return a;
}

#define CP_ASYNC16(dst, src) \
    asm volatile("cp.async.cg.shared.global [%0], [%1], 16;" \
                 :: "r"((uint32_t)(dst)), "l"(src) : "memory")
#define CP_COMMIT() asm volatile("cp.async.commit_group;" ::: "memory")
#define CP_WAIT1()  asm volatile("cp.async.wait_group 1;" ::: "memory")
#define CP_WAIT0()  asm volatile("cp.async.wait_group 0;" ::: "memory")

__device__ __forceinline__ void ldsm4(uint32_t* r, uint32_t addr) {
    asm volatile("ldmatrix.sync.aligned.m8n8.x4.shared.b16 {%0,%1,%2,%3}, [%4];"
                 : "=r"(r[0]), "=r"(r[1]), "=r"(r[2]), "=r"(r[3]) : "r"(addr));
}

__device__ __forceinline__ void mma_tf32(float* c, const uint32_t* a,
                                         uint32_t b0, uint32_t b1) {
    asm volatile(
        "mma.sync.aligned.m16n8k8.row.col.f32.tf32.tf32.f32 "
        "{%0,%1,%2,%3}, {%4,%5,%6,%7}, {%8,%9}, {%0,%1,%2,%3};"
        : "+f"(c[0]), "+f"(c[1]), "+f"(c[2]), "+f"(c[3])
        : "r"(a[0]), "r"(a[1]), "r"(a[2]), "r"(a[3]), "r"(b0), "r"(b1));
}

__device__ __forceinline__ float rtf32(float x) {
    uint32_t r;
    asm("cvt.rna.tf32.f32 %0, %1;" : "=r"(r) : "f"(x));
    return __uint_as_float(r);
}

// ---------------------------------------------------------------------------
// Pre-pass: round fp32 -> tf32 (RNA), all 6 arrays in ONE launch.
// ---------------------------------------------------------------------------
__global__ void tf32_round6(const float4* __restrict__ q,
                            const float4* __restrict__ k,
                            const float4* __restrict__ v,
                            const float4* __restrict__ wq,
                            const float4* __restrict__ wk,
                            const float4* __restrict__ wv,
                            float4* __restrict__ xr,
                            float4* __restrict__ wr) {
    const int y = blockIdx.y;
    const float4* s;
    float4* d;
    int n4;
    if (y < 3) {
        s = (y == 0) ? q : ((y == 1) ? k : v);
        d = xr + (size_t)y * NX4;
        n4 = NX4;
    } else {
        s = (y == 3) ? wq : ((y == 4) ? wk : wv);
        d = wr + (size_t)(y - 3) * NW4;
        n4 = NW4;
    }
    for (int i = blockIdx.x * blockDim.x + threadIdx.x; i < n4;
         i += gridDim.x * blockDim.x) {
        float4 vv = s[i];
        vv.x = rtf32(vv.x); vv.y = rtf32(vv.y);
        vv.z = rtf32(vv.z); vv.w = rtf32(vv.w);
        d[i] = vv;
    }
}

// ---------------------------------------------------------------------------
// tf32 mma.sync projection GEMM (validated R6/R8).
// Q -> fp32 [B,H,S,DK]; K -> RNA-rounded [B,H,S,DK];
// V -> transposed hi/lo split [B,H,DK,S].
// ---------------------------------------------------------------------------
#define PROJ_SMEM (2 * 32768 + 512)

__device__ __forceinline__ void load_chunk(uint32_t stA, uint32_t stB,
                                           const float* __restrict__ X,
                                           const float* __restrict__ W,
                                           int m0, int n0, int k0, int tid) {
#pragma unroll
    for (int i = 0; i < 4; i++) {
        const int q   = tid + i * 256;
        const int row = q >> 3;
        const int c   = q & 7;
        const uint32_t off = (uint32_t)(row * 128) + ((c ^ (row & 7)) << 4);
        CP_ASYNC16(stA + off, X + (size_t)(m0 + row) * D_ + k0 + c * 4);
        CP_ASYNC16(stB + off, W + (size_t)(n0 + row) * D_ + k0 + c * 4);
    }
}

__global__ __launch_bounds__(256, 2)
void proj_mma(const float* __restrict__ bq, const float* __restrict__ bk,
              const float* __restrict__ bv) {
    extern __shared__ char smem[];
    const uint32_t sb = smem_to_u32(smem);

    const int z = blockIdx.z;
    const float* X    = g_Xr + (size_t)z * (B_ * S_) * D_;
    const float* W    = g_Wr + (size_t)z * D_ * D_;
    const float* bias = (z == 0) ? bq : ((z == 1) ? bk : bv);

    const int m0 = blockIdx.y * 128;
    const int n0 = blockIdx.x * 128;
    const int tid = threadIdx.x;
    const int wid = tid >> 5;
    const int lid = tid & 31;
    const int wm = wid >> 2;
    const int wn = wid & 3;

    float* sbias = (float*)(smem + 65536);
    if (tid < 128) sbias[tid] = bias[n0 + tid];

    const int mrow = lid & 7;
    const int msel = lid >> 3;
    const int aRowHalf   = (msel & 1) * 8;
    const int aChunkHalf = msel >> 1;
    const int bRowHalf   = (msel >> 1) * 8;
    const int bChunkHalf = msel & 1;

    float acc[4][4][4];
#pragma unroll
    for (int i = 0; i < 4; i++)
#pragma unroll
        for (int j = 0; j < 4; j++)
#pragma unroll
            for (int r = 0; r < 4; r++) acc[i][j][r] = 0.f;

    load_chunk(sb, sb + 16384, X, W, m0, n0, 0, tid);
    CP_COMMIT();

    for (int c = 0; c < 32; c++) {
        const int cur = c & 1;
        const uint32_t stA = sb + cur * 32768;
        const uint32_t stB = stA + 16384;
        if (c + 1 < 32) {
            const uint32_t nx = sb + (cur ^ 1) * 32768;
            load_chunk(nx, nx + 16384, X, W, m0, n0, (c + 1) * 32, tid);
            CP_COMMIT();
            CP_WAIT1();
        } else {
            CP_WAIT0();
        }
        __syncthreads();

#pragma unroll
        for (int ks = 0; ks < 4; ks++) {
            uint32_t a[4][4];
#pragma unroll
            for (int mf = 0; mf < 4; mf++) {
                const int row = wm * 64 + mf * 16 + aRowHalf + mrow;
                ldsm4(a[mf], stA + row * 128 +
                              (((2 * ks + aChunkHalf) ^ mrow) << 4));
            }
            uint32_t bb[2][4];
#pragma unroll
            for (int nf2 = 0; nf2 < 2; nf2++) {
                const int row = wn * 32 + nf2 * 16 + bRowHalf + mrow;
                ldsm4(bb[nf2], stB + row * 128 +
                               (((2 * ks + bChunkHalf) ^ mrow) << 4));
            }
#pragma unroll
            for (int mf = 0; mf < 4; mf++)
#pragma unroll
                for (int nf = 0; nf < 4; nf++)
                    mma_tf32(acc[mf][nf], a[mf],
                             bb[nf >> 1][(nf & 1) * 2],
                             bb[nf >> 1][(nf & 1) * 2 + 1]);
        }
        __syncthreads();
    }

    // Epilogue: bias + scatter.
    const int g = lid >> 2, t = lid & 3;
#pragma unroll
    for (int mf = 0; mf < 4; mf++) {
        const int m = m0 + wm * 64 + mf * 16 + g;
        const int b = m >> 10;
        const int s = m & 1023;
#pragma unroll
        for (int nf = 0; nf < 4; nf++) {
            const int nl = wn * 32 + nf * 8 + 2 * t;
            const int n = n0 + nl;
            const int h = n >> 6;
            const int d = n & 63;
            const float b0v = sbias[nl], b1v = sbias[nl + 1];
            float v0 = acc[mf][nf][0] + b0v;
            float v1 = acc[mf][nf][1] + b1v;
            float v2 = acc[mf][nf][2] + b0v;
            float v3 = acc[mf][nf][3] + b1v;
            if (z == 2) {
                // V: hi/lo split, transposed [B,H,DK,S]
                const size_t gb = ((size_t)(b * H_ + h) * DK_ + d) * S_;
                float h0 = rtf32(v0), h1 = rtf32(v1), h2 = rtf32(v2), h3 = rtf32(v3);
                g_Vth[gb + s]          = h0;  g_Vtl[gb + s]          = v0 - h0;
                g_Vth[gb + S_ + s]     = h1;  g_Vtl[gb + S_ + s]     = v1 - h1;
                g_Vth[gb + s + 8]      = h2;  g_Vtl[gb + s + 8]      = v2 - h2;
                g_Vth[gb + S_ + s + 8] = h3;  g_Vtl[gb + S_ + s + 8] = v3 - h3;
            } else {
                if (z == 1) {  // K: pre-rounded for attention's tf32 B-operand
                    v0 = rtf32(v0); v1 = rtf32(v1);
                    v2 = rtf32(v2); v3 = rtf32(v3);
                }
                float* out = (z == 0) ? g_Q : g_K;
                const size_t base = (((size_t)(b * H_ + h) * S_) + s) * 64 + d;
                *(float2*)(out + base)          = make_float2(v0, v1);
                *(float2*)(out + base + 8 * 64) = make_float2(v2, v3);
            }
        }
    }
}

// ---------------------------------------------------------------------------
// Flash attention, 2xTF32 (Q split x rounded K; rounded P x split V),
// cp.async double-buffered K/V tiles, warp-local softmax.
// ---------------------------------------------------------------------------
// Stage s (s=0,1) at byte offset s*49152: KH @ +0, VH @ +16384, VL @ +32768.
#define AS_STAGE 49152
#define AS_P     98304      // per warp 4KB: wq*4096
#define AS_MSK   131072
#define ATT_SMEM (131072 + 256)

__device__ __forceinline__ void att_load(uint32_t stg,
                                         const float* __restrict__ Kg,
                                         const float* __restrict__ Vh,
                                         const float* __restrict__ Vl,
                                         int kt, int tid) {
#pragma unroll
    for (int i = 0; i < 4; i++) {
        const int e = tid + i * 256;          // 0..1023 16B chunks
        const int r = e >> 4;                 // 0..63
        const int c = (e & 15) * 4;           // 0..60
        const uint32_t off = ((c >> 5) << 13) + r * 128 +
                             ((((c & 31) >> 2) ^ (r & 7)) << 4);
        CP_ASYNC16(stg + off,         Kg + (size_t)(kt + r) * 64 + c);
        CP_ASYNC16(stg + 16384 + off, Vh + (size_t)r * S_ + kt + c);
        CP_ASYNC16(stg + 32768 + off, Vl + (size_t)r * S_ + kt + c);
    }
}

__global__ __launch_bounds__(256, 1)
void attn_mma(const int* __restrict__ amask, float* __restrict__ out) {
    extern __shared__ char smem[];
    const uint32_t sb = smem_to_u32(smem);
    int* msk = (int*)(smem + AS_MSK);

    const int bh = blockIdx.y;
    const int b  = bh >> 4;
    const int h  = bh & 15;
    const int qb = (gridDim.x - 1) - blockIdx.x;   // heavy blocks first
    const int q0 = qb * 128;
    const int tid = threadIdx.x;
    const int wq  = tid >> 5;
    const int lid = tid & 31;
    const int g = lid >> 2, t = lid & 3;

    const int mrow = lid & 7;
    const int msel = lid >> 3;
    const int aRowHalf   = (msel & 1) * 8;
    const int aChunkHalf = msel >> 1;
    const int bRowHalf   = (msel >> 1) * 8;
    const int bChunkHalf = msel & 1;

    const float* Qg  = g_Q   + (size_t)bh * S_ * DK_;
    const float* Kg  = g_K   + (size_t)bh * S_ * DK_;
    const float* Vhg = g_Vth + (size_t)bh * DK_ * S_;
    const float* Vlg = g_Vtl + (size_t)bh * DK_ * S_;

    // ---- Q A-fragments (hi/lo split), loaded once.
    uint32_t qh[8][4], ql[8][4];
    {
        const float* q0p = Qg + (size_t)(q0 + wq * 16 + g) * 64;
        const float* q8p = q0p + 8 * 64;
#pragma unroll
        for (int ks = 0; ks < 8; ks++) {
            float x0 = q0p[ks * 8 + t];
            float x1 = q8p[ks * 8 + t];
            float x2 = q0p[ks * 8 + t + 4];
            float x3 = q8p[ks * 8 + t + 4];
            float h0 = rtf32(x0), h1 = rtf32(x1), h2 = rtf32(x2), h3 = rtf32(x3);
            qh[ks][0] = __float_as_uint(h0); ql[ks][0] = __float_as_uint(x0 - h0);
            qh[ks][1] = __float_as_uint(h1); ql[ks][1] = __float_as_uint(x1 - h1);
            qh[ks][2] = __float_as_uint(h2); ql[ks][2] = __float_as_uint(x2 - h2);
            qh[ks][3] = __float_as_uint(h3); ql[ks][3] = __float_as_uint(x3 - h3);
        }
    }

    float o[8][4];
    float m0r = -1e30f, m1r = -1e30f, l0r = 0.f, l1r = 0.f;
#pragma unroll
    for (int nf = 0; nf < 8; nf++)
#pragma unroll
        for (int r = 0; r < 4; r++) o[nf][r] = 0.f;

    const int row0 = q0 + wq * 16 + g;
    const int row1 = row0 + 8;
    const int ntiles = (qb + 1) * 2;

    att_load(sb, Kg, Vhg, Vlg, 0, tid);
    CP_COMMIT();

    for (int it = 0; it < ntiles; it++) {
        const int kt = it * 64;
        const uint32_t stg = sb + (it & 1) * AS_STAGE;
        if (it + 1 < ntiles) {
            att_load(sb + ((it + 1) & 1) * AS_STAGE, Kg, Vhg, Vlg, kt + 64, tid);
            CP_COMMIT();
            CP_WAIT1();
        } else {
            CP_WAIT0();
        }
        if (tid < 64) msk[tid] = amask[b * S_ + kt + tid];
        __syncthreads();

        // ---- S = Q K^T  (qh*K + ql*K; K pre-rounded)
        float s[8][4];
#pragma unroll
        for (int nf = 0; nf < 8; nf++)
#pragma unroll
            for (int r = 0; r < 4; r++) s[nf][r] = 0.f;

#pragma unroll
        for (int ks = 0; ks < 8; ks++) {
            const uint32_t coff = ((ks >> 2) << 13) +
                                  (((2 * (ks & 3) + bChunkHalf) ^ mrow) << 4);
#pragma unroll
            for (int nf2 = 0; nf2 < 4; nf2++) {
                const int row = nf2 * 16 + bRowHalf + mrow;
                uint32_t bb[4];
                ldsm4(bb, stg + row * 128 + coff);
#pragma unroll
                for (int half = 0; half < 2; half++) {
                    const int nf = nf2 * 2 + half;
                    mma_tf32(s[nf], qh[ks], bb[half * 2], bb[half * 2 + 1]);
                    mma_tf32(s[nf], ql[ks], bb[half * 2], bb[half * 2 + 1]);
                }
            }
        }

        // ---- mask + scale
#pragma unroll
        for (int nf = 0; nf < 8; nf++) {
            const int c0 = nf * 8 + 2 * t;
            const int kg0 = kt + c0, kg1 = kg0 + 1;
            const bool d0 = (msk[c0] == 0), d1 = (msk[c0 + 1] == 0);
            s[nf][0] = (d0 || kg0 > row0) ? -1e30f : s[nf][0] * 0.125f;
            s[nf][1] = (d1 || kg1 > row0) ? -1e30f : s[nf][1] * 0.125f;
            s[nf][2] = (d0 || kg0 > row1) ? -1e30f : s[nf][2] * 0.125f;
            s[nf][3] = (d1 || kg1 > row1) ? -1e30f : s[nf][3] * 0.125f;
        }

        // ---- online softmax (warp-local over 4 t-lanes)
        float rm0 = -1e30f, rm1 = -1e30f;
#pragma unroll
        for (int nf = 0; nf < 8; nf++) {
            rm0 = fmaxf(rm0, fmaxf(s[nf][0], s[nf][1]));
            rm1 = fmaxf(rm1, fmaxf(s[nf][2], s[nf][3]));
        }
        rm0 = fmaxf(rm0, __shfl_xor_sync(0xffffffffu, rm0, 1));
        rm0 = fmaxf(rm0, __shfl_xor_sync(0xffffffffu, rm0, 2));
        rm1 = fmaxf(rm1, __shfl_xor_sync(0xffffffffu, rm1, 1));
        rm1 = fmaxf(rm1, __shfl_xor_sync(0xffffffffu, rm1, 2));

        const float mn0 = fmaxf(m0r, rm0), mn1 = fmaxf(m1r, rm1);
        const float cr0 = __expf(m0r - mn0), cr1 = __expf(m1r - mn1);
        m0r = mn0; m1r = mn1;

        const uint32_t pW = sb + AS_P + wq * 4096;
        float rs0 = 0.f, rs1 = 0.f;
#pragma unroll
        for (int nf = 0; nf < 8; nf++) {
            const int col = nf * 8 + 2 * t;
            // store ROUNDED p and sum l from the SAME rounded values so the
            // P-rounding bias cancels in O/l.
            float h0 = rtf32(__expf(s[nf][0] - mn0));
            float h1 = rtf32(__expf(s[nf][1] - mn0));
            float h2 = rtf32(__expf(s[nf][2] - mn1));
            float h3 = rtf32(__expf(s[nf][3] - mn1));
            rs0 += h0 + h1;  rs1 += h2 + h3;
            const uint32_t o0 = ((col >> 5) << 11) + g * 128 +
                                ((((col & 31) >> 2) ^ (g & 7)) << 4) + ((col & 3) << 2);
            const uint32_t o1 = ((col >> 5) << 11) + (g + 8) * 128 +
                                ((((col & 31) >> 2) ^ ((g + 8) & 7)) << 4) + ((col & 3) << 2);
            *(float2*)(smem + (pW - sb) + o0) = make_float2(h0, h1);
            *(float2*)(smem + (pW - sb) + o1) = make_float2(h2, h3);
        }
        rs0 += __shfl_xor_sync(0xffffffffu, rs0, 1);
        rs0 += __shfl_xor_sync(0xffffffffu, rs0, 2);
        rs1 += __shfl_xor_sync(0xffffffffu, rs1, 1);
        rs1 += __shfl_xor_sync(0xffffffffu, rs1, 2);
        l0r = l0r * cr0 + rs0;
        l1r = l1r * cr1 + rs1;

#pragma unroll
        for (int nf = 0; nf < 8; nf++) {
            o[nf][0] *= cr0; o[nf][1] *= cr0;
            o[nf][2] *= cr1; o[nf][3] *= cr1;
        }
        __syncwarp();   // P staging visible to this warp's ldsm

        // ---- O += P V  (ph*Vh + ph*Vl; V pre-split)
#pragma unroll
        for (int ks = 0; ks < 8; ks++) {
            uint32_t ah[4];
            const uint32_t ao = ((ks >> 2) << 11) + (aRowHalf + mrow) * 128 +
                                (((2 * (ks & 3) + aChunkHalf) ^ mrow) << 4);
            ldsm4(ah, pW + ao);
            const uint32_t coff = ((ks >> 2) << 13) +
                                  (((2 * (ks & 3) + bChunkHalf) ^ mrow) << 4);
#pragma unroll
            for (int nf2 = 0; nf2 < 4; nf2++) {
                const int row = nf2 * 16 + bRowHalf + mrow;
                uint32_t vh[4], vl[4];
                ldsm4(vh, stg + 16384 + row * 128 + coff);
                ldsm4(vl, stg + 32768 + row * 128 + coff);
#pragma unroll
                for (int half = 0; half < 2; half++) {
                    const int nf = nf2 * 2 + half;
                    mma_tf32(o[nf], ah, vh[half * 2], vh[half * 2 + 1]);
                    mma_tf32(o[nf], ah, vl[half * 2], vl[half * 2 + 1]);
                }
            }
        }
        __syncthreads();   // stage + P reuse safe for next iteration
    }

    // ---- epilogue: O / l -> out [B, S, H*DK]
    const float i0 = 1.f / l0r, i1 = 1.f / l1r;
    float* o0p = out + ((size_t)b * S_ + row0) * D_ + h * DK_;
    float* o1p = out + ((size_t)b * S_ + row1) * D_ + h * DK_;
#pragma unroll
    for (int nf = 0; nf < 8; nf++) {
        const int d = nf * 8 + 2 * t;
        *(float2*)(o0p + d) = make_float2(o[nf][0] * i0, o[nf][1] * i0);
        *(float2*)(o1p + d) = make_float2(o[nf][2] * i1, o[nf][3] * i1);
    }
}

// ---------------------------------------------------------------------------
// Launch
// ---------------------------------------------------------------------------
extern "C" void kernel_launch(void* const* d_in, const int* in_sizes, int n_in,
                              void* d_out, int out_size) {
    const float* query = (const float*)d_in[0];
    const float* key   = (const float*)d_in[1];
    const float* value = (const float*)d_in[2];
    const int*   amask = (const int*)d_in[3];
    const float* Wq    = (const float*)d_in[4];
    const float* bq    = (const float*)d_in[5];
    const float* Wk    = (const float*)d_in[6];
    const float* bk    = (const float*)d_in[7];
    const float* Wv    = (const float*)d_in[8];
    const float* bv    = (const float*)d_in[9];
    float* out = (float*)d_out;

    float* xr;  cudaGetSymbolAddress((void**)&xr, g_Xr);
    float* wr;  cudaGetSymbolAddress((void**)&wr, g_Wr);

    tf32_round6<<<dim3(256, 6), 256>>>(
        (const float4*)query, (const float4*)key, (const float4*)value,
        (const float4*)Wq, (const float4*)Wk, (const float4*)Wv,
        (float4*)xr, (float4*)wr);

    cudaFuncSetAttribute(proj_mma, cudaFuncAttributeMaxDynamicSharedMemorySize,
                         PROJ_SMEM);
    proj_mma<<<dim3(8, 32, 3), 256, PROJ_SMEM>>>(bq, bk, bv);

    cudaFuncSetAttribute(attn_mma, cudaFuncAttributeMaxDynamicSharedMemorySize,
                         ATT_SMEM);
    attn_mma<<<dim3(S_ / 128, B_ * H_), 256, ATT_SMEM>>>(amask, out);
}

// round 11
// speedup vs baseline: 4.1742x; 1.1974x over previous
#include <cuda_runtime.h>
#include <cstdint>

#define B_  4
#define S_  1024
#define D_  1024
#define H_  16
#define DK_ 64
#define NX4 ((B_ * S_ * D_) / 4)
#define NW4 ((D_ * D_) / 4)

// Scratch: Q,K pre-rounded tf32 [B,H,S,DK]; V pre-rounded transposed [B,H,DK,S];
// tf32-rounded copies of X and W.
__device__ float g_Q[B_ * H_ * S_ * DK_];
__device__ float g_K[B_ * H_ * S_ * DK_];
__device__ float g_Vt[B_ * H_ * DK_ * S_];
__device__ float g_Xr[3ull * (B_ * S_) * D_];
__device__ float g_Wr[3ull * D_ * D_];

// ---------------------------------------------------------------------------
// Helpers (sm_80-era PTX only: cp.async, ldmatrix, mma.sync tf32)
// ---------------------------------------------------------------------------
__device__ __forceinline__ uint32_t smem_to_u32(const void* p) {
    uint32_t a;
    asm("{ .reg .u64 t; cvta.to.shared.u64 t, %1; cvt.u32.u64 %0, t; }"
        : "=r"(a) : "l"(p));
    return a;
}

#define CP_ASYNC16(dst, src) \
    asm volatile("cp.async.cg.shared.global [%0], [%1], 16;" \
                 :: "r"((uint32_t)(dst)), "l"(src) : "memory")
#define CP_COMMIT() asm volatile("cp.async.commit_group;" ::: "memory")
#define CP_WAIT1()  asm volatile("cp.async.wait_group 1;" ::: "memory")
#define CP_WAIT0()  asm volatile("cp.async.wait_group 0;" ::: "memory")

__device__ __forceinline__ void ldsm4(uint32_t* r, uint32_t addr) {
    asm volatile("ldmatrix.sync.aligned.m8n8.x4.shared.b16 {%0,%1,%2,%3}, [%4];"
                 : "=r"(r[0]), "=r"(r[1]), "=r"(r[2]), "=r"(r[3]) : "r"(addr));
}

__device__ __forceinline__ void mma_tf32(float* c, const uint32_t* a,
                                         uint32_t b0, uint32_t b1) {
    asm volatile(
        "mma.sync.aligned.m16n8k8.row.col.f32.tf32.tf32.f32 "
        "{%0,%1,%2,%3}, {%4,%5,%6,%7}, {%8,%9}, {%0,%1,%2,%3};"
        : "+f"(c[0]), "+f"(c[1]), "+f"(c[2]), "+f"(c[3])
        : "r"(a[0]), "r"(a[1]), "r"(a[2]), "r"(a[3]), "r"(b0), "r"(b1));
}

__device__ __forceinline__ float rtf32(float x) {
    uint32_t r;
    asm("cvt.rna.tf32.f32 %0, %1;" : "=r"(r) : "f"(x));
    return __uint_as_float(r);
}

// ---------------------------------------------------------------------------
// Pre-pass: round fp32 -> tf32 (RNA), all 6 arrays in ONE launch.
// ---------------------------------------------------------------------------
__global__ void tf32_round6(const float4* __restrict__ q,
                            const float4* __restrict__ k,
                            const float4* __restrict__ v,
                            const float4* __restrict__ wq,
                            const float4* __restrict__ wk,
                            const float4* __restrict__ wv,
                            float4* __restrict__ xr,
                            float4* __restrict__ wr) {
    const int y = blockIdx.y;
    const float4* s;
    float4* d;
    int n4;
    if (y < 3) {
        s = (y == 0) ? q : ((y == 1) ? k : v);
        d = xr + (size_t)y * NX4;
        n4 = NX4;
    } else {
        s = (y == 3) ? wq : ((y == 4) ? wk : wv);
        d = wr + (size_t)(y - 3) * NW4;
        n4 = NW4;
    }
    for (int i = blockIdx.x * blockDim.x + threadIdx.x; i < n4;
         i += gridDim.x * blockDim.x) {
        float4 vv = s[i];
        vv.x = rtf32(vv.x); vv.y = rtf32(vv.y);
        vv.z = rtf32(vv.z); vv.w = rtf32(vv.w);
        d[i] = vv;
    }
}

// ---------------------------------------------------------------------------
// tf32 mma.sync projection GEMM (validated R6/R8/R9).
// Q,K -> RNA-rounded [B,H,S,DK]; V -> RNA-rounded transposed [B,H,DK,S].
// ---------------------------------------------------------------------------
#define PROJ_SMEM (2 * 32768 + 512)

__device__ __forceinline__ void load_chunk(uint32_t stA, uint32_t stB,
                                           const float* __restrict__ X,
                                           const float* __restrict__ W,
                                           int m0, int n0, int k0, int tid) {
#pragma unroll
    for (int i = 0; i < 4; i++) {
        const int q   = tid + i * 256;
        const int row = q >> 3;
        const int c   = q & 7;
        const uint32_t off = (uint32_t)(row * 128) + ((c ^ (row & 7)) << 4);
        CP_ASYNC16(stA + off, X + (size_t)(m0 + row) * D_ + k0 + c * 4);
        CP_ASYNC16(stB + off, W + (size_t)(n0 + row) * D_ + k0 + c * 4);
    }
}

__global__ __launch_bounds__(256, 2)
void proj_mma(const float* __restrict__ bq, const float* __restrict__ bk,
              const float* __restrict__ bv) {
    extern __shared__ char smem[];
    const uint32_t sb = smem_to_u32(smem);

    const int z = blockIdx.z;
    const float* X    = g_Xr + (size_t)z * (B_ * S_) * D_;
    const float* W    = g_Wr + (size_t)z * D_ * D_;
    const float* bias = (z == 0) ? bq : ((z == 1) ? bk : bv);

    const int m0 = blockIdx.y * 128;
    const int n0 = blockIdx.x * 128;
    const int tid = threadIdx.x;
    const int wid = tid >> 5;
    const int lid = tid & 31;
    const int wm = wid >> 2;
    const int wn = wid & 3;

    float* sbias = (float*)(smem + 65536);
    if (tid < 128) sbias[tid] = bias[n0 + tid];

    const int mrow = lid & 7;
    const int msel = lid >> 3;
    const int aRowHalf   = (msel & 1) * 8;
    const int aChunkHalf = msel >> 1;
    const int bRowHalf   = (msel >> 1) * 8;
    const int bChunkHalf = msel & 1;

    float acc[4][4][4];
#pragma unroll
    for (int i = 0; i < 4; i++)
#pragma unroll
        for (int j = 0; j < 4; j++)
#pragma unroll
            for (int r = 0; r < 4; r++) acc[i][j][r] = 0.f;

    load_chunk(sb, sb + 16384, X, W, m0, n0, 0, tid);
    CP_COMMIT();

    for (int c = 0; c < 32; c++) {
        const int cur = c & 1;
        const uint32_t stA = sb + cur * 32768;
        const uint32_t stB = stA + 16384;
        if (c + 1 < 32) {
            const uint32_t nx = sb + (cur ^ 1) * 32768;
            load_chunk(nx, nx + 16384, X, W, m0, n0, (c + 1) * 32, tid);
            CP_COMMIT();
            CP_WAIT1();
        } else {
            CP_WAIT0();
        }
        __syncthreads();

#pragma unroll
        for (int ks = 0; ks < 4; ks++) {
            uint32_t a[4][4];
#pragma unroll
            for (int mf = 0; mf < 4; mf++) {
                const int row = wm * 64 + mf * 16 + aRowHalf + mrow;
                ldsm4(a[mf], stA + row * 128 +
                              (((2 * ks + aChunkHalf) ^ mrow) << 4));
            }
            uint32_t bb[2][4];
#pragma unroll
            for (int nf2 = 0; nf2 < 2; nf2++) {
                const int row = wn * 32 + nf2 * 16 + bRowHalf + mrow;
                ldsm4(bb[nf2], stB + row * 128 +
                               (((2 * ks + bChunkHalf) ^ mrow) << 4));
            }
#pragma unroll
            for (int mf = 0; mf < 4; mf++)
#pragma unroll
                for (int nf = 0; nf < 4; nf++)
                    mma_tf32(acc[mf][nf], a[mf],
                             bb[nf >> 1][(nf & 1) * 2],
                             bb[nf >> 1][(nf & 1) * 2 + 1]);
        }
        __syncthreads();
    }

    // Epilogue: bias + RNA-round + scatter.
    const int g = lid >> 2, t = lid & 3;
#pragma unroll
    for (int mf = 0; mf < 4; mf++) {
        const int m = m0 + wm * 64 + mf * 16 + g;
        const int b = m >> 10;
        const int s = m & 1023;
#pragma unroll
        for (int nf = 0; nf < 4; nf++) {
            const int nl = wn * 32 + nf * 8 + 2 * t;
            const int n = n0 + nl;
            const int h = n >> 6;
            const int d = n & 63;
            const float b0v = sbias[nl], b1v = sbias[nl + 1];
            const float v0 = rtf32(acc[mf][nf][0] + b0v);
            const float v1 = rtf32(acc[mf][nf][1] + b1v);
            const float v2 = rtf32(acc[mf][nf][2] + b0v);
            const float v3 = rtf32(acc[mf][nf][3] + b1v);
            if (z == 2) {
                // V: transposed [B,H,DK,S]
                const size_t gb = ((size_t)(b * H_ + h) * DK_ + d) * S_;
                g_Vt[gb + s]          = v0;
                g_Vt[gb + S_ + s]     = v1;
                g_Vt[gb + s + 8]      = v2;
                g_Vt[gb + S_ + s + 8] = v3;
            } else {
                float* out = (z == 0) ? g_Q : g_K;
                const size_t base = (((size_t)(b * H_ + h) * S_) + s) * 64 + d;
                *(float2*)(out + base)          = make_float2(v0, v1);
                *(float2*)(out + base + 8 * 64) = make_float2(v2, v3);
            }
        }
    }
}

// ---------------------------------------------------------------------------
// Flash attention, pure 1xTF32 mma.sync (all operands RNA-pre-rounded),
// cp.async double-buffered K/V tiles, warp-local softmax, 2 CTAs/SM.
// ---------------------------------------------------------------------------
// Stage s (s=0,1) at byte offset s*32768: K @ +0, Vt @ +16384.
#define AS_STAGE 32768
#define AS_P     65536      // per warp 4KB: wq*4096
#define AS_MSK   98304
#define ATT_SMEM (98304 + 256)

__device__ __forceinline__ void att_load(uint32_t stg,
                                         const float* __restrict__ Kg,
                                         const float* __restrict__ Vt,
                                         int kt, int tid) {
#pragma unroll
    for (int i = 0; i < 4; i++) {
        const int e = tid + i * 256;          // 0..1023 16B chunks
        const int r = e >> 4;                 // 0..63
        const int c = (e & 15) * 4;           // 0..60
        const uint32_t off = ((c >> 5) << 13) + r * 128 +
                             ((((c & 31) >> 2) ^ (r & 7)) << 4);
        CP_ASYNC16(stg + off,         Kg + (size_t)(kt + r) * 64 + c);
        CP_ASYNC16(stg + 16384 + off, Vt + (size_t)r * S_ + kt + c);
    }
}

__global__ __launch_bounds__(256, 2)
void attn_mma(const int* __restrict__ amask, float* __restrict__ out) {
    extern __shared__ char smem[];
    const uint32_t sb = smem_to_u32(smem);
    int* msk = (int*)(smem + AS_MSK);

    const int bh = blockIdx.y;
    const int b  = bh >> 4;
    const int h  = bh & 15;
    const int qb = (gridDim.x - 1) - blockIdx.x;   // heavy blocks first
    const int q0 = qb * 128;
    const int tid = threadIdx.x;
    const int wq  = tid >> 5;
    const int lid = tid & 31;
    const int g = lid >> 2, t = lid & 3;

    const int mrow = lid & 7;
    const int msel = lid >> 3;
    const int aRowHalf   = (msel & 1) * 8;
    const int aChunkHalf = msel >> 1;
    const int bRowHalf   = (msel >> 1) * 8;
    const int bChunkHalf = msel & 1;

    const float* Qg  = g_Q  + (size_t)bh * S_ * DK_;
    const float* Kg  = g_K  + (size_t)bh * S_ * DK_;
    const float* Vtg = g_Vt + (size_t)bh * DK_ * S_;

    // ---- Q A-fragments (pre-rounded in proj), loaded once.
    uint32_t qh[8][4];
    {
        const float* q0p = Qg + (size_t)(q0 + wq * 16 + g) * 64;
        const float* q8p = q0p + 8 * 64;
#pragma unroll
        for (int ks = 0; ks < 8; ks++) {
            qh[ks][0] = __float_as_uint(q0p[ks * 8 + t]);
            qh[ks][1] = __float_as_uint(q8p[ks * 8 + t]);
            qh[ks][2] = __float_as_uint(q0p[ks * 8 + t + 4]);
            qh[ks][3] = __float_as_uint(q8p[ks * 8 + t + 4]);
        }
    }

    float o[8][4];
    float m0r = -1e30f, m1r = -1e30f, l0r = 0.f, l1r = 0.f;
#pragma unroll
    for (int nf = 0; nf < 8; nf++)
#pragma unroll
        for (int r = 0; r < 4; r++) o[nf][r] = 0.f;

    const int row0 = q0 + wq * 16 + g;
    const int row1 = row0 + 8;
    const int ntiles = (qb + 1) * 2;

    att_load(sb, Kg, Vtg, 0, tid);
    CP_COMMIT();

    for (int it = 0; it < ntiles; it++) {
        const int kt = it * 64;
        const uint32_t stg = sb + (it & 1) * AS_STAGE;
        if (it + 1 < ntiles) {
            att_load(sb + ((it + 1) & 1) * AS_STAGE, Kg, Vtg, kt + 64, tid);
            CP_COMMIT();
            CP_WAIT1();
        } else {
            CP_WAIT0();
        }
        if (tid < 64) msk[tid] = amask[b * S_ + kt + tid];
        __syncthreads();

        // ---- S = Q K^T
        float s[8][4];
#pragma unroll
        for (int nf = 0; nf < 8; nf++)
#pragma unroll
            for (int r = 0; r < 4; r++) s[nf][r] = 0.f;

#pragma unroll
        for (int ks = 0; ks < 8; ks++) {
            const uint32_t coff = ((ks >> 2) << 13) +
                                  (((2 * (ks & 3) + bChunkHalf) ^ mrow) << 4);
#pragma unroll
            for (int nf2 = 0; nf2 < 4; nf2++) {
                const int row = nf2 * 16 + bRowHalf + mrow;
                uint32_t bb[4];
                ldsm4(bb, stg + row * 128 + coff);
                mma_tf32(s[nf2 * 2],     qh[ks], bb[0], bb[1]);
                mma_tf32(s[nf2 * 2 + 1], qh[ks], bb[2], bb[3]);
            }
        }

        // ---- mask + scale
#pragma unroll
        for (int nf = 0; nf < 8; nf++) {
            const int c0 = nf * 8 + 2 * t;
            const int kg0 = kt + c0, kg1 = kg0 + 1;
            const bool d0 = (msk[c0] == 0), d1 = (msk[c0 + 1] == 0);
            s[nf][0] = (d0 || kg0 > row0) ? -1e30f : s[nf][0] * 0.125f;
            s[nf][1] = (d1 || kg1 > row0) ? -1e30f : s[nf][1] * 0.125f;
            s[nf][2] = (d0 || kg0 > row1) ? -1e30f : s[nf][2] * 0.125f;
            s[nf][3] = (d1 || kg1 > row1) ? -1e30f : s[nf][3] * 0.125f;
        }

        // ---- online softmax (warp-local over 4 t-lanes)
        float rm0 = -1e30f, rm1 = -1e30f;
#pragma unroll
        for (int nf = 0; nf < 8; nf++) {
            rm0 = fmaxf(rm0, fmaxf(s[nf][0], s[nf][1]));
            rm1 = fmaxf(rm1, fmaxf(s[nf][2], s[nf][3]));
        }
        rm0 = fmaxf(rm0, __shfl_xor_sync(0xffffffffu, rm0, 1));
        rm0 = fmaxf(rm0, __shfl_xor_sync(0xffffffffu, rm0, 2));
        rm1 = fmaxf(rm1, __shfl_xor_sync(0xffffffffu, rm1, 1));
        rm1 = fmaxf(rm1, __shfl_xor_sync(0xffffffffu, rm1, 2));

        const float mn0 = fmaxf(m0r, rm0), mn1 = fmaxf(m1r, rm1);
        const float cr0 = __expf(m0r - mn0), cr1 = __expf(m1r - mn1);
        m0r = mn0; m1r = mn1;

        const uint32_t pW = sb + AS_P + wq * 4096;
        float rs0 = 0.f, rs1 = 0.f;
#pragma unroll
        for (int nf = 0; nf < 8; nf++) {
            const int col = nf * 8 + 2 * t;
            // store ROUNDED p; sum l from the SAME rounded values so the
            // P-rounding bias cancels in O/l.
            float h0 = rtf32(__expf(s[nf][0] - mn0));
            float h1 = rtf32(__expf(s[nf][1] - mn0));
            float h2 = rtf32(__expf(s[nf][2] - mn1));
            float h3 = rtf32(__expf(s[nf][3] - mn1));
            rs0 += h0 + h1;  rs1 += h2 + h3;
            const uint32_t o0 = ((col >> 5) << 11) + g * 128 +
                                ((((col & 31) >> 2) ^ (g & 7)) << 4) + ((col & 3) << 2);
            const uint32_t o1 = ((col >> 5) << 11) + (g + 8) * 128 +
                                ((((col & 31) >> 2) ^ ((g + 8) & 7)) << 4) + ((col & 3) << 2);
            *(float2*)(smem + (pW - sb) + o0) = make_float2(h0, h1);
            *(float2*)(smem + (pW - sb) + o1) = make_float2(h2, h3);
        }
        rs0 += __shfl_xor_sync(0xffffffffu, rs0, 1);
        rs0 += __shfl_xor_sync(0xffffffffu, rs0, 2);
        rs1 += __shfl_xor_sync(0xffffffffu, rs1, 1);
        rs1 += __shfl_xor_sync(0xffffffffu, rs1, 2);
        l0r = l0r * cr0 + rs0;
        l1r = l1r * cr1 + rs1;

#pragma unroll
        for (int nf = 0; nf < 8; nf++) {
            o[nf][0] *= cr0; o[nf][1] *= cr0;
            o[nf][2] *= cr1; o[nf][3] *= cr1;
        }
        __syncwarp();   // P staging visible to this warp's ldsm

        // ---- O += P V
#pragma unroll
        for (int ks = 0; ks < 8; ks++) {
            uint32_t ah[4];
            const uint32_t ao = ((ks >> 2) << 11) + (aRowHalf + mrow) * 128 +
                                (((2 * (ks & 3) + aChunkHalf) ^ mrow) << 4);
            ldsm4(ah, pW + ao);
            const uint32_t coff = ((ks >> 2) << 13) +
                                  (((2 * (ks & 3) + bChunkHalf) ^ mrow) << 4);
#pragma unroll
            for (int nf2 = 0; nf2 < 4; nf2++) {
                const int row = nf2 * 16 + bRowHalf + mrow;
                uint32_t vv[4];
                ldsm4(vv, stg + 16384 + row * 128 + coff);
                mma_tf32(o[nf2 * 2],     ah, vv[0], vv[1]);
                mma_tf32(o[nf2 * 2 + 1], ah, vv[2], vv[3]);
            }
        }
        __syncthreads();   // stage + P reuse safe for next iteration
    }

    // ---- epilogue: O / l -> out [B, S, H*DK]
    const float i0 = 1.f / l0r, i1 = 1.f / l1r;
    float* o0p = out + ((size_t)b * S_ + row0) * D_ + h * DK_;
    float* o1p = out + ((size_t)b * S_ + row1) * D_ + h * DK_;
#pragma unroll
    for (int nf = 0; nf < 8; nf++) {
        const int d = nf * 8 + 2 * t;
        *(float2*)(o0p + d) = make_float2(o[nf][0] * i0, o[nf][1] * i0);
        *(float2*)(o1p + d) = make_float2(o[nf][2] * i1, o[nf][3] * i1);
    }
}

// ---------------------------------------------------------------------------
// Launch
// ---------------------------------------------------------------------------
extern "C" void kernel_launch(void* const* d_in, const int* in_sizes, int n_in,
                              void* d_out, int out_size) {
    const float* query = (const float*)d_in[0];
    const float* key   = (const float*)d_in[1];
    const float* value = (const float*)d_in[2];
    const int*   amask = (const int*)d_in[3];
    const float* Wq    = (const float*)d_in[4];
    const float* bq    = (const float*)d_in[5];
    const float* Wk    = (const float*)d_in[6];
    const float* bk    = (const float*)d_in[7];
    const float* Wv    = (const float*)d_in[8];
    const float* bv    = (const float*)d_in[9];
    float* out = (float*)d_out;

    float* xr;  cudaGetSymbolAddress((void**)&xr, g_Xr);
    float* wr;  cudaGetSymbolAddress((void**)&wr, g_Wr);

    tf32_round6<<<dim3(256, 6), 256>>>(
        (const float4*)query, (const float4*)key, (const float4*)value,
        (const float4*)Wq, (const float4*)Wk, (const float4*)Wv,
        (float4*)xr, (float4*)wr);

    cudaFuncSetAttribute(proj_mma, cudaFuncAttributeMaxDynamicSharedMemorySize,
                         PROJ_SMEM);
    proj_mma<<<dim3(8, 32, 3), 256, PROJ_SMEM>>>(bq, bk, bv);

    cudaFuncSetAttribute(attn_mma, cudaFuncAttributeMaxDynamicSharedMemorySize,
                         ATT_SMEM);
    attn_mma<<<dim3(S_ / 128, B_ * H_), 256, ATT_SMEM>>>(amask, out);
}

// round 13
// speedup vs baseline: 4.3863x; 1.0508x over previous
#include <cuda_runtime.h>
#include <cstdint>

#define B_  4
#define S_  1024
#define D_  1024
#define H_  16
#define DK_ 64

// Scratch: Q,K pre-rounded tf32 [B,H,S,DK]; V pre-rounded transposed [B,H,DK,S].
__device__ float g_Q[B_ * H_ * S_ * DK_];
__device__ float g_K[B_ * H_ * S_ * DK_];
__device__ float g_Vt[B_ * H_ * DK_ * S_];

// ---------------------------------------------------------------------------
// Helpers (sm_80-era PTX only: cp.async, ldmatrix, mma.sync tf32)
// ---------------------------------------------------------------------------
__device__ __forceinline__ uint32_t smem_to_u32(const void* p) {
    uint32_t a;
    asm("{ .reg .u64 t; cvta.to.shared.u64 t, %1; cvt.u32.u64 %0, t; }"
        : "=r"(a) : "l"(p));
    return a;
}

#define CP_ASYNC16(dst, src) \
    asm volatile("cp.async.cg.shared.global [%0], [%1], 16;" \
                 :: "r"((uint32_t)(dst)), "l"(src) : "memory")
#define CP_COMMIT() asm volatile("cp.async.commit_group;" ::: "memory")
#define CP_WAIT1()  asm volatile("cp.async.wait_group 1;" ::: "memory")
#define CP_WAIT0()  asm volatile("cp.async.wait_group 0;" ::: "memory")

__device__ __forceinline__ void ldsm4(uint32_t* r, uint32_t addr) {
    asm volatile("ldmatrix.sync.aligned.m8n8.x4.shared.b16 {%0,%1,%2,%3}, [%4];"
                 : "=r"(r[0]), "=r"(r[1]), "=r"(r[2]), "=r"(r[3]) : "r"(addr));
}

__device__ __forceinline__ void mma_tf32(float* c, const uint32_t* a,
                                         uint32_t b0, uint32_t b1) {
    asm volatile(
        "mma.sync.aligned.m16n8k8.row.col.f32.tf32.tf32.f32 "
        "{%0,%1,%2,%3}, {%4,%5,%6,%7}, {%8,%9}, {%0,%1,%2,%3};"
        : "+f"(c[0]), "+f"(c[1]), "+f"(c[2]), "+f"(c[3])
        : "r"(a[0]), "r"(a[1]), "r"(a[2]), "r"(a[3]), "r"(b0), "r"(b1));
}

__device__ __forceinline__ float rtf32(float x) {
    uint32_t r;
    asm("cvt.rna.tf32.f32 %0, %1;" : "=r"(r) : "f"(x));
    return __uint_as_float(r);
}

__device__ __forceinline__ uint32_t rtf32u(uint32_t x) {
    uint32_t r;
    asm("cvt.rna.tf32.f32 %0, %1;" : "=r"(r) : "f"(__uint_as_float(x)));
    return r;
}

// ---------------------------------------------------------------------------
// tf32 mma.sync projection GEMM. Reads RAW fp32 inputs; RNA-rounds each
// A/B fragment in registers post-ldsm (numerically identical to the old
// separate rounding pre-pass, which is now deleted).
// Q,K -> RNA-rounded [B,H,S,DK]; V -> RNA-rounded transposed [B,H,DK,S].
// ---------------------------------------------------------------------------
#define PROJ_SMEM (2 * 32768 + 512)

__device__ __forceinline__ void load_chunk(uint32_t stA, uint32_t stB,
                                           const float* __restrict__ X,
                                           const float* __restrict__ W,
                                           int m0, int n0, int k0, int tid) {
#pragma unroll
    for (int i = 0; i < 4; i++) {
        const int q   = tid + i * 256;
        const int row = q >> 3;
        const int c   = q & 7;
        const uint32_t off = (uint32_t)(row * 128) + ((c ^ (row & 7)) << 4);
        CP_ASYNC16(stA + off, X + (size_t)(m0 + row) * D_ + k0 + c * 4);
        CP_ASYNC16(stB + off, W + (size_t)(n0 + row) * D_ + k0 + c * 4);
    }
}

__global__ __launch_bounds__(256, 2)
void proj_mma(const float* __restrict__ Xq, const float* __restrict__ Xk,
              const float* __restrict__ Xv,
              const float* __restrict__ Wq, const float* __restrict__ bq,
              const float* __restrict__ Wk, const float* __restrict__ bk,
              const float* __restrict__ Wv, const float* __restrict__ bv) {
    extern __shared__ char smem[];
    const uint32_t sb = smem_to_u32(smem);

    const int z = blockIdx.z;
    const float* X    = (z == 0) ? Xq : ((z == 1) ? Xk : Xv);
    const float* W    = (z == 0) ? Wq : ((z == 1) ? Wk : Wv);
    const float* bias = (z == 0) ? bq : ((z == 1) ? bk : bv);

    const int m0 = blockIdx.y * 128;
    const int n0 = blockIdx.x * 128;
    const int tid = threadIdx.x;
    const int wid = tid >> 5;
    const int lid = tid & 31;
    const int wm = wid >> 2;
    const int wn = wid & 3;

    float* sbias = (float*)(smem + 65536);
    if (tid < 128) sbias[tid] = bias[n0 + tid];

    const int mrow = lid & 7;
    const int msel = lid >> 3;
    const int aRowHalf   = (msel & 1) * 8;
    const int aChunkHalf = msel >> 1;
    const int bRowHalf   = (msel >> 1) * 8;
    const int bChunkHalf = msel & 1;

    float acc[4][4][4];
#pragma unroll
    for (int i = 0; i < 4; i++)
#pragma unroll
        for (int j = 0; j < 4; j++)
#pragma unroll
            for (int r = 0; r < 4; r++) acc[i][j][r] = 0.f;

    load_chunk(sb, sb + 16384, X, W, m0, n0, 0, tid);
    CP_COMMIT();

    for (int c = 0; c < 32; c++) {
        const int cur = c & 1;
        const uint32_t stA = sb + cur * 32768;
        const uint32_t stB = stA + 16384;
        if (c + 1 < 32) {
            const uint32_t nx = sb + (cur ^ 1) * 32768;
            load_chunk(nx, nx + 16384, X, W, m0, n0, (c + 1) * 32, tid);
            CP_COMMIT();
            CP_WAIT1();
        } else {
            CP_WAIT0();
        }
        __syncthreads();

#pragma unroll
        for (int ks = 0; ks < 4; ks++) {
            uint32_t a[4][4];
#pragma unroll
            for (int mf = 0; mf < 4; mf++) {
                const int row = wm * 64 + mf * 16 + aRowHalf + mrow;
                ldsm4(a[mf], stA + row * 128 +
                              (((2 * ks + aChunkHalf) ^ mrow) << 4));
#pragma unroll
                for (int j = 0; j < 4; j++) a[mf][j] = rtf32u(a[mf][j]);
            }
            uint32_t bb[2][4];
#pragma unroll
            for (int nf2 = 0; nf2 < 2; nf2++) {
                const int row = wn * 32 + nf2 * 16 + bRowHalf + mrow;
                ldsm4(bb[nf2], stB + row * 128 +
                               (((2 * ks + bChunkHalf) ^ mrow) << 4));
#pragma unroll
                for (int j = 0; j < 4; j++) bb[nf2][j] = rtf32u(bb[nf2][j]);
            }
#pragma unroll
            for (int mf = 0; mf < 4; mf++)
#pragma unroll
                for (int nf = 0; nf < 4; nf++)
                    mma_tf32(acc[mf][nf], a[mf],
                             bb[nf >> 1][(nf & 1) * 2],
                             bb[nf >> 1][(nf & 1) * 2 + 1]);
        }
        __syncthreads();
    }

    // Epilogue: bias + RNA-round + scatter.
    const int g = lid >> 2, t = lid & 3;
#pragma unroll
    for (int mf = 0; mf < 4; mf++) {
        const int m = m0 + wm * 64 + mf * 16 + g;
        const int b = m >> 10;
        const int s = m & 1023;
#pragma unroll
        for (int nf = 0; nf < 4; nf++) {
            const int nl = wn * 32 + nf * 8 + 2 * t;
            const int n = n0 + nl;
            const int h = n >> 6;
            const int d = n & 63;
            const float b0v = sbias[nl], b1v = sbias[nl + 1];
            const float v0 = rtf32(acc[mf][nf][0] + b0v);
            const float v1 = rtf32(acc[mf][nf][1] + b1v);
            const float v2 = rtf32(acc[mf][nf][2] + b0v);
            const float v3 = rtf32(acc[mf][nf][3] + b1v);
            if (z == 2) {
                // V: transposed [B,H,DK,S]
                const size_t gb = ((size_t)(b * H_ + h) * DK_ + d) * S_;
                g_Vt[gb + s]          = v0;
                g_Vt[gb + S_ + s]     = v1;
                g_Vt[gb + s + 8]      = v2;
                g_Vt[gb + S_ + s + 8] = v3;
            } else {
                float* out = (z == 0) ? g_Q : g_K;
                const size_t base = (((size_t)(b * H_ + h) * S_) + s) * 64 + d;
                *(float2*)(out + base)          = make_float2(v0, v1);
                *(float2*)(out + base + 8 * 64) = make_float2(v2, v3);
            }
        }
    }
}

// ---------------------------------------------------------------------------
// Flash attention, pure 1xTF32 mma.sync (all operands RNA-pre-rounded),
// cp.async double-buffered K/V tiles, warp-local softmax, 2 CTAs/SM,
// persistent full-row mask, fully-masked warp-tiles skipped.
// ---------------------------------------------------------------------------
// Stage s (s=0,1) at byte offset s*32768: K @ +0, Vt @ +16384.
#define AS_STAGE 32768
#define AS_P     65536      // per warp 4KB: wq*4096
#define AS_MSK   98304      // persistent mask: 1024 ints (4KB)
#define ATT_SMEM (98304 + 4096)

__device__ __forceinline__ void att_load(uint32_t stg,
                                         const float* __restrict__ Kg,
                                         const float* __restrict__ Vt,
                                         int kt, int tid) {
#pragma unroll
    for (int i = 0; i < 4; i++) {
        const int e = tid + i * 256;          // 0..1023 16B chunks
        const int r = e >> 4;                 // 0..63
        const int c = (e & 15) * 4;           // 0..60
        const uint32_t off = ((c >> 5) << 13) + r * 128 +
                             ((((c & 31) >> 2) ^ (r & 7)) << 4);
        CP_ASYNC16(stg + off,         Kg + (size_t)(kt + r) * 64 + c);
        CP_ASYNC16(stg + 16384 + off, Vt + (size_t)r * S_ + kt + c);
    }
}

__global__ __launch_bounds__(256, 2)
void attn_mma(const int* __restrict__ amask, float* __restrict__ out) {
    extern __shared__ char smem[];
    const uint32_t sb = smem_to_u32(smem);
    int* msk = (int*)(smem + AS_MSK);

    const int bh = blockIdx.y;
    const int b  = bh >> 4;
    const int h  = bh & 15;
    const int qb = (gridDim.x - 1) - blockIdx.x;   // heavy blocks first
    const int q0 = qb * 128;
    const int tid = threadIdx.x;
    const int wq  = tid >> 5;
    const int lid = tid & 31;
    const int g = lid >> 2, t = lid & 3;

    const int mrow = lid & 7;
    const int msel = lid >> 3;
    const int aRowHalf   = (msel & 1) * 8;
    const int aChunkHalf = msel >> 1;
    const int bRowHalf   = (msel >> 1) * 8;
    const int bChunkHalf = msel & 1;

    const float* Qg  = g_Q  + (size_t)bh * S_ * DK_;
    const float* Kg  = g_K  + (size_t)bh * S_ * DK_;
    const float* Vtg = g_Vt + (size_t)bh * DK_ * S_;

    // ---- persistent mask for this batch row (whole sequence, loaded once)
#pragma unroll
    for (int i = 0; i < 4; i++) msk[tid + i * 256] = amask[b * S_ + tid + i * 256];

    // ---- Q A-fragments (pre-rounded in proj), loaded once.
    uint32_t qh[8][4];
    {
        const float* q0p = Qg + (size_t)(q0 + wq * 16 + g) * 64;
        const float* q8p = q0p + 8 * 64;
#pragma unroll
        for (int ks = 0; ks < 8; ks++) {
            qh[ks][0] = __float_as_uint(q0p[ks * 8 + t]);
            qh[ks][1] = __float_as_uint(q8p[ks * 8 + t]);
            qh[ks][2] = __float_as_uint(q0p[ks * 8 + t + 4]);
            qh[ks][3] = __float_as_uint(q8p[ks * 8 + t + 4]);
        }
    }

    float o[8][4];
    float m0r = -1e30f, m1r = -1e30f, l0r = 0.f, l1r = 0.f;
#pragma unroll
    for (int nf = 0; nf < 8; nf++)
#pragma unroll
        for (int r = 0; r < 4; r++) o[nf][r] = 0.f;

    const int row0 = q0 + wq * 16 + g;
    const int row1 = row0 + 8;
    const int wrow_max = q0 + wq * 16 + 15;   // warp's max q row
    const int ntiles = (qb + 1) * 2;

    att_load(sb, Kg, Vtg, 0, tid);
    CP_COMMIT();

    for (int it = 0; it < ntiles; it++) {
        const int kt = it * 64;
        const uint32_t stg = sb + (it & 1) * AS_STAGE;
        if (it + 1 < ntiles) {
            att_load(sb + ((it + 1) & 1) * AS_STAGE, Kg, Vtg, kt + 64, tid);
            CP_COMMIT();
            CP_WAIT1();
        } else {
            CP_WAIT0();
        }
        __syncthreads();

        // Fully-masked warp-tile (all rows < all cols): provably a no-op on
        // m/l/o — skip all compute, keep the barriers.
        if (wrow_max >= kt) {
            // ---- S = Q K^T
            float s[8][4];
#pragma unroll
            for (int nf = 0; nf < 8; nf++)
#pragma unroll
                for (int r = 0; r < 4; r++) s[nf][r] = 0.f;

#pragma unroll
            for (int ks = 0; ks < 8; ks++) {
                const uint32_t coff = ((ks >> 2) << 13) +
                                      (((2 * (ks & 3) + bChunkHalf) ^ mrow) << 4);
#pragma unroll
                for (int nf2 = 0; nf2 < 4; nf2++) {
                    const int row = nf2 * 16 + bRowHalf + mrow;
                    uint32_t bb[4];
                    ldsm4(bb, stg + row * 128 + coff);
                    mma_tf32(s[nf2 * 2],     qh[ks], bb[0], bb[1]);
                    mma_tf32(s[nf2 * 2 + 1], qh[ks], bb[2], bb[3]);
                }
            }

            // ---- mask + scale (persistent mask)
#pragma unroll
            for (int nf = 0; nf < 8; nf++) {
                const int c0 = nf * 8 + 2 * t;
                const int kg0 = kt + c0, kg1 = kg0 + 1;
                const bool d0 = (msk[kg0] == 0), d1 = (msk[kg1] == 0);
                s[nf][0] = (d0 || kg0 > row0) ? -1e30f : s[nf][0] * 0.125f;
                s[nf][1] = (d1 || kg1 > row0) ? -1e30f : s[nf][1] * 0.125f;
                s[nf][2] = (d0 || kg0 > row1) ? -1e30f : s[nf][2] * 0.125f;
                s[nf][3] = (d1 || kg1 > row1) ? -1e30f : s[nf][3] * 0.125f;
            }

            // ---- online softmax (warp-local over 4 t-lanes)
            float rm0 = -1e30f, rm1 = -1e30f;
#pragma unroll
            for (int nf = 0; nf < 8; nf++) {
                rm0 = fmaxf(rm0, fmaxf(s[nf][0], s[nf][1]));
                rm1 = fmaxf(rm1, fmaxf(s[nf][2], s[nf][3]));
            }
            rm0 = fmaxf(rm0, __shfl_xor_sync(0xffffffffu, rm0, 1));
            rm0 = fmaxf(rm0, __shfl_xor_sync(0xffffffffu, rm0, 2));
            rm1 = fmaxf(rm1, __shfl_xor_sync(0xffffffffu, rm1, 1));
            rm1 = fmaxf(rm1, __shfl_xor_sync(0xffffffffu, rm1, 2));

            const float mn0 = fmaxf(m0r, rm0), mn1 = fmaxf(m1r, rm1);
            const float cr0 = __expf(m0r - mn0), cr1 = __expf(m1r - mn1);
            m0r = mn0; m1r = mn1;

            const uint32_t pW = sb + AS_P + wq * 4096;
            float rs0 = 0.f, rs1 = 0.f;
#pragma unroll
            for (int nf = 0; nf < 8; nf++) {
                const int col = nf * 8 + 2 * t;
                // store ROUNDED p; sum l from the SAME rounded values so the
                // P-rounding bias cancels in O/l.
                float h0 = rtf32(__expf(s[nf][0] - mn0));
                float h1 = rtf32(__expf(s[nf][1] - mn0));
                float h2 = rtf32(__expf(s[nf][2] - mn1));
                float h3 = rtf32(__expf(s[nf][3] - mn1));
                rs0 += h0 + h1;  rs1 += h2 + h3;
                const uint32_t o0 = ((col >> 5) << 11) + g * 128 +
                                    ((((col & 31) >> 2) ^ (g & 7)) << 4) + ((col & 3) << 2);
                const uint32_t o1 = ((col >> 5) << 11) + (g + 8) * 128 +
                                    ((((col & 31) >> 2) ^ ((g + 8) & 7)) << 4) + ((col & 3) << 2);
                *(float2*)(smem + (pW - sb) + o0) = make_float2(h0, h1);
                *(float2*)(smem + (pW - sb) + o1) = make_float2(h2, h3);
            }
            rs0 += __shfl_xor_sync(0xffffffffu, rs0, 1);
            rs0 += __shfl_xor_sync(0xffffffffu, rs0, 2);
            rs1 += __shfl_xor_sync(0xffffffffu, rs1, 1);
            rs1 += __shfl_xor_sync(0xffffffffu, rs1, 2);
            l0r = l0r * cr0 + rs0;
            l1r = l1r * cr1 + rs1;

#pragma unroll
            for (int nf = 0; nf < 8; nf++) {
                o[nf][0] *= cr0; o[nf][1] *= cr0;
                o[nf][2] *= cr1; o[nf][3] *= cr1;
            }
            __syncwarp();   // P staging visible to this warp's ldsm

            // ---- O += P V
#pragma unroll
            for (int ks = 0; ks < 8; ks++) {
                uint32_t ah[4];
                const uint32_t ao = ((ks >> 2) << 11) + (aRowHalf + mrow) * 128 +
                                    (((2 * (ks & 3) + aChunkHalf) ^ mrow) << 4);
                ldsm4(ah, pW + ao);
                const uint32_t coff = ((ks >> 2) << 13) +
                                      (((2 * (ks & 3) + bChunkHalf) ^ mrow) << 4);
#pragma unroll
                for (int nf2 = 0; nf2 < 4; nf2++) {
                    const int row = nf2 * 16 + bRowHalf + mrow;
                    uint32_t vv[4];
                    ldsm4(vv, stg + 16384 + row * 128 + coff);
                    mma_tf32(o[nf2 * 2],     ah, vv[0], vv[1]);
                    mma_tf32(o[nf2 * 2 + 1], ah, vv[2], vv[3]);
                }
            }
        }
        __syncthreads();   // stage + P reuse safe for next iteration
    }

    // ---- epilogue: O / l -> out [B, S, H*DK]
    const float i0 = 1.f / l0r, i1 = 1.f / l1r;
    float* o0p = out + ((size_t)b * S_ + row0) * D_ + h * DK_;
    float* o1p = out + ((size_t)b * S_ + row1) * D_ + h * DK_;
#pragma unroll
    for (int nf = 0; nf < 8; nf++) {
        const int d = nf * 8 + 2 * t;
        *(float2*)(o0p + d) = make_float2(o[nf][0] * i0, o[nf][1] * i0);
        *(float2*)(o1p + d) = make_float2(o[nf][2] * i1, o[nf][3] * i1);
    }
}

// ---------------------------------------------------------------------------
// Launch
// ---------------------------------------------------------------------------
extern "C" void kernel_launch(void* const* d_in, const int* in_sizes, int n_in,
                              void* d_out, int out_size) {
    const float* query = (const float*)d_in[0];
    const float* key   = (const float*)d_in[1];
    const float* value = (const float*)d_in[2];
    const int*   amask = (const int*)d_in[3];
    const float* Wq    = (const float*)d_in[4];
    const float* bq    = (const float*)d_in[5];
    const float* Wk    = (const float*)d_in[6];
    const float* bk    = (const float*)d_in[7];
    const float* Wv    = (const float*)d_in[8];
    const float* bv    = (const float*)d_in[9];
    float* out = (float*)d_out;

    cudaFuncSetAttribute(proj_mma, cudaFuncAttributeMaxDynamicSharedMemorySize,
                         PROJ_SMEM);
    proj_mma<<<dim3(8, 32, 3), 256, PROJ_SMEM>>>(query, key, value,
                                                 Wq, bq, Wk, bk, Wv, bv);

    cudaFuncSetAttribute(attn_mma, cudaFuncAttributeMaxDynamicSharedMemorySize,
                         ATT_SMEM);
    attn_mma<<<dim3(S_ / 128, B_ * H_), 256, ATT_SMEM>>>(amask, out);
}

// round 14
// speedup vs baseline: 4.3908x; 1.0010x over previous
#include <cuda_runtime.h>
#include <cstdint>

#define B_  4
#define S_  1024
#define D_  1024
#define H_  16
#define DK_ 64
#define NX4 ((B_ * S_ * D_) / 4)
#define NW4 ((D_ * D_) / 4)

// Scratch: Q,K pre-rounded tf32 [B,H,S,DK]; V pre-rounded transposed [B,H,DK,S];
// tf32-rounded copies of X and W.
__device__ float g_Q[B_ * H_ * S_ * DK_];
__device__ float g_K[B_ * H_ * S_ * DK_];
__device__ float g_Vt[B_ * H_ * DK_ * S_];
__device__ float g_Xr[3ull * (B_ * S_) * D_];
__device__ float g_Wr[3ull * D_ * D_];

// ---------------------------------------------------------------------------
// Helpers (sm_80-era PTX only: cp.async, ldmatrix, mma.sync tf32)
// ---------------------------------------------------------------------------
__device__ __forceinline__ uint32_t smem_to_u32(const void* p) {
    uint32_t a;
    asm("{ .reg .u64 t; cvta.to.shared.u64 t, %1; cvt.u32.u64 %0, t; }"
        : "=r"(a) : "l"(p));
    return a;
}

#define CP_ASYNC16(dst, src) \
    asm volatile("cp.async.cg.shared.global [%0], [%1], 16;" \
                 :: "r"((uint32_t)(dst)), "l"(src) : "memory")
#define CP_COMMIT() asm volatile("cp.async.commit_group;" ::: "memory")
#define CP_WAIT1()  asm volatile("cp.async.wait_group 1;" ::: "memory")
#define CP_WAIT0()  asm volatile("cp.async.wait_group 0;" ::: "memory")

__device__ __forceinline__ void ldsm4(uint32_t* r, uint32_t addr) {
    asm volatile("ldmatrix.sync.aligned.m8n8.x4.shared.b16 {%0,%1,%2,%3}, [%4];"
                 : "=r"(r[0]), "=r"(r[1]), "=r"(r[2]), "=r"(r[3]) : "r"(addr));
}

__device__ __forceinline__ void mma_tf32(float* c, const uint32_t* a,
                                         uint32_t b0, uint32_t b1) {
    asm volatile(
        "mma.sync.aligned.m16n8k8.row.col.f32.tf32.tf32.f32 "
        "{%0,%1,%2,%3}, {%4,%5,%6,%7}, {%8,%9}, {%0,%1,%2,%3};"
        : "+f"(c[0]), "+f"(c[1]), "+f"(c[2]), "+f"(c[3])
        : "r"(a[0]), "r"(a[1]), "r"(a[2]), "r"(a[3]), "r"(b0), "r"(b1));
}

__device__ __forceinline__ float rtf32(float x) {
    uint32_t r;
    asm("cvt.rna.tf32.f32 %0, %1;" : "=r"(r) : "f"(x));
    return __uint_as_float(r);
}

// ---------------------------------------------------------------------------
// Pre-pass: round fp32 -> tf32 (RNA), all 6 arrays in ONE launch.
// (Restored from R11: in-register fragment rounding in proj broke the
// mainloop's ILP — measured ~+70us on proj. Numerically identical.)
// ---------------------------------------------------------------------------
__global__ void tf32_round6(const float4* __restrict__ q,
                            const float4* __restrict__ k,
                            const float4* __restrict__ v,
                            const float4* __restrict__ wq,
                            const float4* __restrict__ wk,
                            const float4* __restrict__ wv,
                            float4* __restrict__ xr,
                            float4* __restrict__ wr) {
    const int y = blockIdx.y;
    const float4* s;
    float4* d;
    int n4;
    if (y < 3) {
        s = (y == 0) ? q : ((y == 1) ? k : v);
        d = xr + (size_t)y * NX4;
        n4 = NX4;
    } else {
        s = (y == 3) ? wq : ((y == 4) ? wk : wv);
        d = wr + (size_t)(y - 3) * NW4;
        n4 = NW4;
    }
    for (int i = blockIdx.x * blockDim.x + threadIdx.x; i < n4;
         i += gridDim.x * blockDim.x) {
        float4 vv = s[i];
        vv.x = rtf32(vv.x); vv.y = rtf32(vv.y);
        vv.z = rtf32(vv.z); vv.w = rtf32(vv.w);
        d[i] = vv;
    }
}

// ---------------------------------------------------------------------------
// tf32 mma.sync projection GEMM (R11 form: reads pre-rounded inputs).
// Q,K -> RNA-rounded [B,H,S,DK]; V -> RNA-rounded transposed [B,H,DK,S].
// ---------------------------------------------------------------------------
#define PROJ_SMEM (2 * 32768 + 512)

__device__ __forceinline__ void load_chunk(uint32_t stA, uint32_t stB,
                                           const float* __restrict__ X,
                                           const float* __restrict__ W,
                                           int m0, int n0, int k0, int tid) {
#pragma unroll
    for (int i = 0; i < 4; i++) {
        const int q   = tid + i * 256;
        const int row = q >> 3;
        const int c   = q & 7;
        const uint32_t off = (uint32_t)(row * 128) + ((c ^ (row & 7)) << 4);
        CP_ASYNC16(stA + off, X + (size_t)(m0 + row) * D_ + k0 + c * 4);
        CP_ASYNC16(stB + off, W + (size_t)(n0 + row) * D_ + k0 + c * 4);
    }
}

__global__ __launch_bounds__(256, 2)
void proj_mma(const float* __restrict__ bq, const float* __restrict__ bk,
              const float* __restrict__ bv) {
    extern __shared__ char smem[];
    const uint32_t sb = smem_to_u32(smem);

    const int z = blockIdx.z;
    const float* X    = g_Xr + (size_t)z * (B_ * S_) * D_;
    const float* W    = g_Wr + (size_t)z * D_ * D_;
    const float* bias = (z == 0) ? bq : ((z == 1) ? bk : bv);

    const int m0 = blockIdx.y * 128;
    const int n0 = blockIdx.x * 128;
    const int tid = threadIdx.x;
    const int wid = tid >> 5;
    const int lid = tid & 31;
    const int wm = wid >> 2;
    const int wn = wid & 3;

    float* sbias = (float*)(smem + 65536);
    if (tid < 128) sbias[tid] = bias[n0 + tid];

    const int mrow = lid & 7;
    const int msel = lid >> 3;
    const int aRowHalf   = (msel & 1) * 8;
    const int aChunkHalf = msel >> 1;
    const int bRowHalf   = (msel >> 1) * 8;
    const int bChunkHalf = msel & 1;

    float acc[4][4][4];
#pragma unroll
    for (int i = 0; i < 4; i++)
#pragma unroll
        for (int j = 0; j < 4; j++)
#pragma unroll
            for (int r = 0; r < 4; r++) acc[i][j][r] = 0.f;

    load_chunk(sb, sb + 16384, X, W, m0, n0, 0, tid);
    CP_COMMIT();

    for (int c = 0; c < 32; c++) {
        const int cur = c & 1;
        const uint32_t stA = sb + cur * 32768;
        const uint32_t stB = stA + 16384;
        if (c + 1 < 32) {
            const uint32_t nx = sb + (cur ^ 1) * 32768;
            load_chunk(nx, nx + 16384, X, W, m0, n0, (c + 1) * 32, tid);
            CP_COMMIT();
            CP_WAIT1();
        } else {
            CP_WAIT0();
        }
        __syncthreads();

#pragma unroll
        for (int ks = 0; ks < 4; ks++) {
            uint32_t a[4][4];
#pragma unroll
            for (int mf = 0; mf < 4; mf++) {
                const int row = wm * 64 + mf * 16 + aRowHalf + mrow;
                ldsm4(a[mf], stA + row * 128 +
                              (((2 * ks + aChunkHalf) ^ mrow) << 4));
            }
            uint32_t bb[2][4];
#pragma unroll
            for (int nf2 = 0; nf2 < 2; nf2++) {
                const int row = wn * 32 + nf2 * 16 + bRowHalf + mrow;
                ldsm4(bb[nf2], stB + row * 128 +
                               (((2 * ks + bChunkHalf) ^ mrow) << 4));
            }
#pragma unroll
            for (int mf = 0; mf < 4; mf++)
#pragma unroll
                for (int nf = 0; nf < 4; nf++)
                    mma_tf32(acc[mf][nf], a[mf],
                             bb[nf >> 1][(nf & 1) * 2],
                             bb[nf >> 1][(nf & 1) * 2 + 1]);
        }
        __syncthreads();
    }

    // Epilogue: bias + RNA-round + scatter.
    const int g = lid >> 2, t = lid & 3;
#pragma unroll
    for (int mf = 0; mf < 4; mf++) {
        const int m = m0 + wm * 64 + mf * 16 + g;
        const int b = m >> 10;
        const int s = m & 1023;
#pragma unroll
        for (int nf = 0; nf < 4; nf++) {
            const int nl = wn * 32 + nf * 8 + 2 * t;
            const int n = n0 + nl;
            const int h = n >> 6;
            const int d = n & 63;
            const float b0v = sbias[nl], b1v = sbias[nl + 1];
            const float v0 = rtf32(acc[mf][nf][0] + b0v);
            const float v1 = rtf32(acc[mf][nf][1] + b1v);
            const float v2 = rtf32(acc[mf][nf][2] + b0v);
            const float v3 = rtf32(acc[mf][nf][3] + b1v);
            if (z == 2) {
                // V: transposed [B,H,DK,S]
                const size_t gb = ((size_t)(b * H_ + h) * DK_ + d) * S_;
                g_Vt[gb + s]          = v0;
                g_Vt[gb + S_ + s]     = v1;
                g_Vt[gb + s + 8]      = v2;
                g_Vt[gb + S_ + s + 8] = v3;
            } else {
                float* out = (z == 0) ? g_Q : g_K;
                const size_t base = (((size_t)(b * H_ + h) * S_) + s) * 64 + d;
                *(float2*)(out + base)          = make_float2(v0, v1);
                *(float2*)(out + base + 8 * 64) = make_float2(v2, v3);
            }
        }
    }
}

// ---------------------------------------------------------------------------
// Flash attention (R13 form, unchanged): pure 1xTF32 mma.sync, cp.async
// double-buffered K/V tiles, warp-local softmax, 2 CTAs/SM, persistent mask,
// fully-masked warp-tiles skipped.
// ---------------------------------------------------------------------------
// Stage s (s=0,1) at byte offset s*32768: K @ +0, Vt @ +16384.
#define AS_STAGE 32768
#define AS_P     65536      // per warp 4KB: wq*4096
#define AS_MSK   98304      // persistent mask: 1024 ints (4KB)
#define ATT_SMEM (98304 + 4096)

__device__ __forceinline__ void att_load(uint32_t stg,
                                         const float* __restrict__ Kg,
                                         const float* __restrict__ Vt,
                                         int kt, int tid) {
#pragma unroll
    for (int i = 0; i < 4; i++) {
        const int e = tid + i * 256;          // 0..1023 16B chunks
        const int r = e >> 4;                 // 0..63
        const int c = (e & 15) * 4;           // 0..60
        const uint32_t off = ((c >> 5) << 13) + r * 128 +
                             ((((c & 31) >> 2) ^ (r & 7)) << 4);
        CP_ASYNC16(stg + off,         Kg + (size_t)(kt + r) * 64 + c);
        CP_ASYNC16(stg + 16384 + off, Vt + (size_t)r * S_ + kt + c);
    }
}

__global__ __launch_bounds__(256, 2)
void attn_mma(const int* __restrict__ amask, float* __restrict__ out) {
    extern __shared__ char smem[];
    const uint32_t sb = smem_to_u32(smem);
    int* msk = (int*)(smem + AS_MSK);

    const int bh = blockIdx.y;
    const int b  = bh >> 4;
    const int h  = bh & 15;
    const int qb = (gridDim.x - 1) - blockIdx.x;   // heavy blocks first
    const int q0 = qb * 128;
    const int tid = threadIdx.x;
    const int wq  = tid >> 5;
    const int lid = tid & 31;
    const int g = lid >> 2, t = lid & 3;

    const int mrow = lid & 7;
    const int msel = lid >> 3;
    const int aRowHalf   = (msel & 1) * 8;
    const int aChunkHalf = msel >> 1;
    const int bRowHalf   = (msel >> 1) * 8;
    const int bChunkHalf = msel & 1;

    const float* Qg  = g_Q  + (size_t)bh * S_ * DK_;
    const float* Kg  = g_K  + (size_t)bh * S_ * DK_;
    const float* Vtg = g_Vt + (size_t)bh * DK_ * S_;

    // ---- persistent mask for this batch row (whole sequence, loaded once)
#pragma unroll
    for (int i = 0; i < 4; i++) msk[tid + i * 256] = amask[b * S_ + tid + i * 256];

    // ---- Q A-fragments (pre-rounded in proj), loaded once.
    uint32_t qh[8][4];
    {
        const float* q0p = Qg + (size_t)(q0 + wq * 16 + g) * 64;
        const float* q8p = q0p + 8 * 64;
#pragma unroll
        for (int ks = 0; ks < 8; ks++) {
            qh[ks][0] = __float_as_uint(q0p[ks * 8 + t]);
            qh[ks][1] = __float_as_uint(q8p[ks * 8 + t]);
            qh[ks][2] = __float_as_uint(q0p[ks * 8 + t + 4]);
            qh[ks][3] = __float_as_uint(q8p[ks * 8 + t + 4]);
        }
    }

    float o[8][4];
    float m0r = -1e30f, m1r = -1e30f, l0r = 0.f, l1r = 0.f;
#pragma unroll
    for (int nf = 0; nf < 8; nf++)
#pragma unroll
        for (int r = 0; r < 4; r++) o[nf][r] = 0.f;

    const int row0 = q0 + wq * 16 + g;
    const int row1 = row0 + 8;
    const int wrow_max = q0 + wq * 16 + 15;   // warp's max q row
    const int ntiles = (qb + 1) * 2;

    att_load(sb, Kg, Vtg, 0, tid);
    CP_COMMIT();

    for (int it = 0; it < ntiles; it++) {
        const int kt = it * 64;
        const uint32_t stg = sb + (it & 1) * AS_STAGE;
        if (it + 1 < ntiles) {
            att_load(sb + ((it + 1) & 1) * AS_STAGE, Kg, Vtg, kt + 64, tid);
            CP_COMMIT();
            CP_WAIT1();
        } else {
            CP_WAIT0();
        }
        __syncthreads();

        // Fully-masked warp-tile (all rows < all cols): provably a no-op on
        // m/l/o — skip all compute, keep the barriers.
        if (wrow_max >= kt) {
            // ---- S = Q K^T
            float s[8][4];
#pragma unroll
            for (int nf = 0; nf < 8; nf++)
#pragma unroll
                for (int r = 0; r < 4; r++) s[nf][r] = 0.f;

#pragma unroll
            for (int ks = 0; ks < 8; ks++) {
                const uint32_t coff = ((ks >> 2) << 13) +
                                      (((2 * (ks & 3) + bChunkHalf) ^ mrow) << 4);
#pragma unroll
                for (int nf2 = 0; nf2 < 4; nf2++) {
                    const int row = nf2 * 16 + bRowHalf + mrow;
                    uint32_t bb[4];
                    ldsm4(bb, stg + row * 128 + coff);
                    mma_tf32(s[nf2 * 2],     qh[ks], bb[0], bb[1]);
                    mma_tf32(s[nf2 * 2 + 1], qh[ks], bb[2], bb[3]);
                }
            }

            // ---- mask + scale (persistent mask)
#pragma unroll
            for (int nf = 0; nf < 8; nf++) {
                const int c0 = nf * 8 + 2 * t;
                const int kg0 = kt + c0, kg1 = kg0 + 1;
                const bool d0 = (msk[kg0] == 0), d1 = (msk[kg1] == 0);
                s[nf][0] = (d0 || kg0 > row0) ? -1e30f : s[nf][0] * 0.125f;
                s[nf][1] = (d1 || kg1 > row0) ? -1e30f : s[nf][1] * 0.125f;
                s[nf][2] = (d0 || kg0 > row1) ? -1e30f : s[nf][2] * 0.125f;
                s[nf][3] = (d1 || kg1 > row1) ? -1e30f : s[nf][3] * 0.125f;
            }

            // ---- online softmax (warp-local over 4 t-lanes)
            float rm0 = -1e30f, rm1 = -1e30f;
#pragma unroll
            for (int nf = 0; nf < 8; nf++) {
                rm0 = fmaxf(rm0, fmaxf(s[nf][0], s[nf][1]));
                rm1 = fmaxf(rm1, fmaxf(s[nf][2], s[nf][3]));
            }
            rm0 = fmaxf(rm0, __shfl_xor_sync(0xffffffffu, rm0, 1));
            rm0 = fmaxf(rm0, __shfl_xor_sync(0xffffffffu, rm0, 2));
            rm1 = fmaxf(rm1, __shfl_xor_sync(0xffffffffu, rm1, 1));
            rm1 = fmaxf(rm1, __shfl_xor_sync(0xffffffffu, rm1, 2));

            const float mn0 = fmaxf(m0r, rm0), mn1 = fmaxf(m1r, rm1);
            const float cr0 = __expf(m0r - mn0), cr1 = __expf(m1r - mn1);
            m0r = mn0; m1r = mn1;

            const uint32_t pW = sb + AS_P + wq * 4096;
            float rs0 = 0.f, rs1 = 0.f;
#pragma unroll
            for (int nf = 0; nf < 8; nf++) {
                const int col = nf * 8 + 2 * t;
                // store ROUNDED p; sum l from the SAME rounded values so the
                // P-rounding bias cancels in O/l.
                float h0 = rtf32(__expf(s[nf][0] - mn0));
                float h1 = rtf32(__expf(s[nf][1] - mn0));
                float h2 = rtf32(__expf(s[nf][2] - mn1));
                float h3 = rtf32(__expf(s[nf][3] - mn1));
                rs0 += h0 + h1;  rs1 += h2 + h3;
                const uint32_t o0 = ((col >> 5) << 11) + g * 128 +
                                    ((((col & 31) >> 2) ^ (g & 7)) << 4) + ((col & 3) << 2);
                const uint32_t o1 = ((col >> 5) << 11) + (g + 8) * 128 +
                                    ((((col & 31) >> 2) ^ ((g + 8) & 7)) << 4) + ((col & 3) << 2);
                *(float2*)(smem + (pW - sb) + o0) = make_float2(h0, h1);
                *(float2*)(smem + (pW - sb) + o1) = make_float2(h2, h3);
            }
            rs0 += __shfl_xor_sync(0xffffffffu, rs0, 1);
            rs0 += __shfl_xor_sync(0xffffffffu, rs0, 2);
            rs1 += __shfl_xor_sync(0xffffffffu, rs1, 1);
            rs1 += __shfl_xor_sync(0xffffffffu, rs1, 2);
            l0r = l0r * cr0 + rs0;
            l1r = l1r * cr1 + rs1;

#pragma unroll
            for (int nf = 0; nf < 8; nf++) {
                o[nf][0] *= cr0; o[nf][1] *= cr0;
                o[nf][2] *= cr1; o[nf][3] *= cr1;
            }
            __syncwarp();   // P staging visible to this warp's ldsm

            // ---- O += P V
#pragma unroll
            for (int ks = 0; ks < 8; ks++) {
                uint32_t ah[4];
                const uint32_t ao = ((ks >> 2) << 11) + (aRowHalf + mrow) * 128 +
                                    (((2 * (ks & 3) + aChunkHalf) ^ mrow) << 4);
                ldsm4(ah, pW + ao);
                const uint32_t coff = ((ks >> 2) << 13) +
                                      (((2 * (ks & 3) + bChunkHalf) ^ mrow) << 4);
#pragma unroll
                for (int nf2 = 0; nf2 < 4; nf2++) {
                    const int row = nf2 * 16 + bRowHalf + mrow;
                    uint32_t vv[4];
                    ldsm4(vv, stg + 16384 + row * 128 + coff);
                    mma_tf32(o[nf2 * 2],     ah, vv[0], vv[1]);
                    mma_tf32(o[nf2 * 2 + 1], ah, vv[2], vv[3]);
                }
            }
        }
        __syncthreads();   // stage + P reuse safe for next iteration
    }

    // ---- epilogue: O / l -> out [B, S, H*DK]
    const float i0 = 1.f / l0r, i1 = 1.f / l1r;
    float* o0p = out + ((size_t)b * S_ + row0) * D_ + h * DK_;
    float* o1p = out + ((size_t)b * S_ + row1) * D_ + h * DK_;
#pragma unroll
    for (int nf = 0; nf < 8; nf++) {
        const int d = nf * 8 + 2 * t;
        *(float2*)(o0p + d) = make_float2(o[nf][0] * i0, o[nf][1] * i0);
        *(float2*)(o1p + d) = make_float2(o[nf][2] * i1, o[nf][3] * i1);
    }
}

// ---------------------------------------------------------------------------
// Launch
// ---------------------------------------------------------------------------
extern "C" void kernel_launch(void* const* d_in, const int* in_sizes, int n_in,
                              void* d_out, int out_size) {
    const float* query = (const float*)d_in[0];
    const float* key   = (const float*)d_in[1];
    const float* value = (const float*)d_in[2];
    const int*   amask = (const int*)d_in[3];
    const float* Wq    = (const float*)d_in[4];
    const float* bq    = (const float*)d_in[5];
    const float* Wk    = (const float*)d_in[6];
    const float* bk    = (const float*)d_in[7];
    const float* Wv    = (const float*)d_in[8];
    const float* bv    = (const float*)d_in[9];
    float* out = (float*)d_out;

    float* xr;  cudaGetSymbolAddress((void**)&xr, g_Xr);
    float* wr;  cudaGetSymbolAddress((void**)&wr, g_Wr);

    tf32_round6<<<dim3(256, 6), 256>>>(
        (const float4*)query, (const float4*)key, (const float4*)value,
        (const float4*)Wq, (const float4*)Wk, (const float4*)Wv,
        (float4*)xr, (float4*)wr);

    cudaFuncSetAttribute(proj_mma, cudaFuncAttributeMaxDynamicSharedMemorySize,
                         PROJ_SMEM);
    proj_mma<<<dim3(8, 32, 3), 256, PROJ_SMEM>>>(bq, bk, bv);

    cudaFuncSetAttribute(attn_mma, cudaFuncAttributeMaxDynamicSharedMemorySize,
                         ATT_SMEM);
    attn_mma<<<dim3(S_ / 128, B_ * H_), 256, ATT_SMEM>>>(amask, out);
}